// round 14
// baseline (speedup 1.0000x reference)
#include <cuda_runtime.h>
#include <cstdint>

#define DIM 768
#define HEADS 12
#define DH 64
#define INNER 768
#define BATCH 2
#define SEQ 1024
#define ROWS (BATCH*SEQ)      // 2048
#define NN (SEQ*SEQ)          // 1048576
#define BH (BATCH*HEADS)      // 24
#define SCALE 0.125f
#define LN_EPS 1e-5f
#define PADC 36               // floats per 32-float chunk row (144B, 16B mult)
#define NSPLIT 4
#define NB_PER (8/NSPLIT)     // k-tiles per dots block
#define KSPLIT_AV 2

// ---------------- scratch (device globals; no allocation allowed) ----------
__device__ float g_xn[ROWS*DIM];               // tf32-rounded
__device__ float g_wq[3*INNER*DIM];            // tf32-rounded w_qkv
__device__ float g_wo[DIM*INNER];              // tf32-rounded w_out
__device__ float g_q[BH*SEQ*DH];               // tf32-rounded
__device__ float g_k[BH*SEQ*DH];               // tf32-rounded
__device__ float g_vt[BH*DH*SEQ];              // tf32-rounded, [bh][d][n]
__device__ float g_attn[(size_t)BH*NN];        // full fp32 exp(logits)
__device__ float g_P[(size_t)BH*NN];           // tf32-rounded
__device__ float g_psum[BH*SEQ*NSPLIT];
__device__ float g_Oa[ROWS*INNER];             // av partial (K first half)
__device__ float g_Ob[ROWS*INNER];             // av partial (K second half)
__device__ float g_O[ROWS*INNER];              // summed, tf32-rounded
__device__ float g_M[HEADS*HEADS];

// ---------------- helpers --------------------------------------------------
__device__ __forceinline__ uint32_t smem_u32(const void* p) {
    uint32_t a;
    asm("{ .reg .u64 t; cvta.to.shared.u64 t, %1; cvt.u32.u64 %0, t; }"
        : "=r"(a) : "l"(p));
    return a;
}
__device__ __forceinline__ float to_tf32(float x) {
    float y;
    asm("cvt.rna.tf32.f32 %0, %1;" : "=f"(y) : "f"(x));
    return y;
}
__device__ __forceinline__ void mma_tf32(float* c, const uint32_t* a, const uint32_t* b) {
    asm volatile(
        "mma.sync.aligned.m16n8k8.row.col.f32.tf32.tf32.f32 "
        "{%0,%1,%2,%3}, {%4,%5,%6,%7}, {%8,%9}, {%0,%1,%2,%3};"
        : "+f"(c[0]), "+f"(c[1]), "+f"(c[2]), "+f"(c[3])
        : "r"(a[0]), "r"(a[1]), "r"(a[2]), "r"(a[3]), "r"(b[0]), "r"(b[1]));
}
#define LDSM_X4(r0, r1, r2, r3, addr) \
    asm volatile("ldmatrix.sync.aligned.m8n8.x4.shared.b16 {%0,%1,%2,%3}, [%4];" \
        : "=r"(r0), "=r"(r1), "=r"(r2), "=r"(r3) : "r"(addr))
#define CP_ASYNC16(dst, src) \
    asm volatile("cp.async.cg.shared.global [%0], [%1], 16;" \
        :: "r"(dst), "l"(src) : "memory")
#define CP_COMMIT()  asm volatile("cp.async.commit_group;" ::: "memory")
#define CP_WAIT0()   asm volatile("cp.async.wait_group 0;" ::: "memory")

// ---- pipelined tf32 mma core: D[128,BN]=A[128,K]@B[BN,K]^T ----------------
// ldmatrix fragment loads, one barrier per chunk.
template<int BN>
__device__ __forceinline__ void gemm_pipe(float* Cacc,
                                          const float* __restrict__ A, int lda,
                                          const float* __restrict__ B, int ldb,
                                          int K, float* As, float* Bs) {
    constexpr int WC = BN / 32;
    constexpr int WR = 8 / WC;
    constexpr int WM = 128 / WR;
    constexpr int MT = WM / 16;
    constexpr int BTPR = 256 / BN;
    constexpr int BSEG = 32 / BTPR;

    const int tid = threadIdx.x, wid = tid >> 5, lane = tid & 31;
    const int wr = wid / WC, wc = wid % WC;
    const int wm0 = wr * WM, wn0 = wc * 32;
    const int arow = tid >> 1, ac0 = (tid & 1) * 16;
    const int brow = tid / BTPR, bc0 = (tid % BTPR) * BSEG;
    const int lq = lane & 7, lt = lane >> 3;

    const uint32_t sa = smem_u32(As);
    const uint32_t sb = smem_u32(Bs);
    const uint32_t a0 = sa + (uint32_t)((wm0 + (lt & 1) * 8 + lq) * PADC + (lt >> 1) * 4) * 4u;
    const uint32_t b0 = sb + (uint32_t)((wn0 + (lt >> 1) * 8 + lq) * PADC + (lt & 1) * 4) * 4u;
    const int nch = K >> 5;

    auto prefetch = [&](int c, int buf) {
        const float* ap = A + (size_t)arow * lda + c * 32 + ac0;
        uint32_t da = sa + (uint32_t)(buf * 128 * PADC + arow * PADC + ac0) * 4u;
#pragma unroll
        for (int i = 0; i < 4; i++) CP_ASYNC16(da + i * 16, ap + i * 4);
        const float* bp = B + (size_t)brow * ldb + c * 32 + bc0;
        uint32_t db = sb + (uint32_t)(buf * BN * PADC + brow * PADC + bc0) * 4u;
#pragma unroll
        for (int i = 0; i < BSEG / 4; i++) CP_ASYNC16(db + i * 16, bp + i * 4);
        CP_COMMIT();
    };

    prefetch(0, 0);
    for (int c = 0; c < nch; c++) {
        CP_WAIT0();
        __syncthreads();
        if (c + 1 < nch) prefetch(c + 1, (c + 1) & 1);
        const uint32_t ab = a0 + (uint32_t)(c & 1) * (128 * PADC * 4);
        const uint32_t bb = b0 + (uint32_t)(c & 1) * (BN * PADC * 4);
#pragma unroll
        for (int ks = 0; ks < 4; ks++) {
            uint32_t af[MT][4], bf[2][4];
#pragma unroll
            for (int mi = 0; mi < MT; mi++)
                LDSM_X4(af[mi][0], af[mi][1], af[mi][2], af[mi][3],
                        ab + mi * (16 * PADC * 4) + ks * 32);
#pragma unroll
            for (int p = 0; p < 2; p++)
                LDSM_X4(bf[p][0], bf[p][1], bf[p][2], bf[p][3],
                        bb + p * (16 * PADC * 4) + ks * 32);
#pragma unroll
            for (int mi = 0; mi < MT; mi++)
#pragma unroll
                for (int ni = 0; ni < 4; ni++)
                    mma_tf32(&Cacc[(mi * 4 + ni) * 4], af[mi], &bf[ni >> 1][(ni & 1) * 2]);
        }
    }
    __syncthreads();
}

#define SMEM128 ((2*128 + 2*128) * PADC * 4)   // 73728 B
#define SMEM64  ((2*128 + 2*64)  * PADC * 4)   // 55296 B

// ---------------- tf32 pre-round (both weight tensors, one launch) ---------
#define WQ4 ((3*INNER*DIM)/4)
#define WO4 ((DIM*INNER)/4)
__global__ __launch_bounds__(256) void round_w2(const float* __restrict__ wq,
                                                const float* __restrict__ wo) {
    int i = blockIdx.x * 256 + threadIdx.x;
    const float4* src;
    float4* dst;
    int j;
    if (i < WQ4) { src = (const float4*)wq; j = i;        dst = (float4*)g_wq; }
    else if (i < WQ4 + WO4) { src = (const float4*)wo; j = i - WQ4; dst = (float4*)g_wo; }
    else return;
    float4 v = src[j];
    v.x = to_tf32(v.x); v.y = to_tf32(v.y); v.z = to_tf32(v.z); v.w = to_tf32(v.w);
    dst[j] = v;
}

// ---------------- LayerNorm (stores tf32-rounded xn) -----------------------
__global__ __launch_bounds__(256) void ln_kernel(const float* __restrict__ x,
                                                 const float* __restrict__ gam,
                                                 const float* __restrict__ bet) {
    int row = blockIdx.x;
    const float* xr = x + (size_t)row * DIM;
    float vals[3];
    float s = 0.f, s2 = 0.f;
#pragma unroll
    for (int i = 0; i < 3; i++) {
        float v = xr[threadIdx.x + i * 256];
        vals[i] = v; s += v; s2 += v * v;
    }
    __shared__ float sh1[32], sh2[32];
#pragma unroll
    for (int o = 16; o > 0; o >>= 1) {
        s  += __shfl_down_sync(0xffffffffu, s,  o);
        s2 += __shfl_down_sync(0xffffffffu, s2, o);
    }
    int lane = threadIdx.x & 31, wid = threadIdx.x >> 5;
    if (lane == 0) { sh1[wid] = s; sh2[wid] = s2; }
    __syncthreads();
    if (wid == 0) {
        s  = (lane < 8) ? sh1[lane] : 0.f;
        s2 = (lane < 8) ? sh2[lane] : 0.f;
#pragma unroll
        for (int o = 4; o > 0; o >>= 1) {
            s  += __shfl_down_sync(0xffffffffu, s,  o);
            s2 += __shfl_down_sync(0xffffffffu, s2, o);
        }
        if (lane == 0) { sh1[0] = s; sh2[0] = s2; }
    }
    __syncthreads();
    float mean = sh1[0] * (1.f / DIM);
    float var  = sh2[0] * (1.f / DIM) - mean * mean;
    float rstd = rsqrtf(var + LN_EPS);
#pragma unroll
    for (int i = 0; i < 3; i++) {
        int c = threadIdx.x + i * 256;
        g_xn[(size_t)row * DIM + c] = to_tf32((vals[i] - mean) * rstd * gam[c] + bet[c]);
    }
}

// ---------------- M = (-0.5*theta) @ gnn_w ---------------------------------
__global__ void m_kernel(const float* __restrict__ theta, const float* __restrict__ w) {
    int t = threadIdx.x;
    if (t < HEADS * HEADS) {
        int i = t / HEADS, m = t % HEADS;
        float s = 0.f;
#pragma unroll
        for (int j = 0; j < HEADS; j++)
            s += (-0.5f * theta[i * HEADS + j]) * w[j * HEADS + m];
        g_M[t] = s;
    }
}

// ---------------- QKV: BN=64 tiles, 3 CTAs/SM, scatter to heads ------------
// Each 64-wide N-tile is 64-aligned -> lies in exactly one of q/k/v and one head.
__global__ __launch_bounds__(256, 3) void qkv_tc() {
    extern __shared__ float dynsm[];
    float* As = dynsm;
    float* Bs = dynsm + 2 * 128 * PADC;
    int nb = blockIdx.x, mb = blockIdx.y;
    float Cacc[32] = {};
    gemm_pipe<64>(Cacc, g_xn + (size_t)mb * 128 * DIM, DIM,
                  g_wq + (size_t)nb * 64 * DIM, DIM, DIM, As, Bs);

    const int lane = threadIdx.x & 31, wid = threadIdx.x >> 5;
    const int g = lane >> 2, t = lane & 3;
    const int wr = wid >> 1, wc = wid & 1;
    const int which = (nb * 64) / INNER;
    const int h = ((nb * 64) % INNER) >> 6;
#pragma unroll
    for (int mi = 0; mi < 2; mi++) {
        int gi0 = mb * 128 + wr * 32 + mi * 16 + g;
#pragma unroll
        for (int ni = 0; ni < 4; ni++) {
            int d = wc * 32 + ni * 8 + 2 * t;
            const float* cp = &Cacc[(mi * 4 + ni) * 4];
#pragma unroll
            for (int half = 0; half < 2; half++) {
                int gi = gi0 + half * 8;
                int b = gi >> 10, n = gi & 1023;
                float c0 = to_tf32(cp[half * 2]), c1 = to_tf32(cp[half * 2 + 1]);
                if (which < 2) {
                    float* dst = (which == 0) ? g_q : g_k;
                    *(float2*)(dst + ((size_t)(b * HEADS + h) * SEQ + n) * DH + d)
                        = make_float2(c0, c1);
                } else {
                    float* p = g_vt + (size_t)(b * HEADS + h) * DH * SEQ + n;
                    p[(size_t)d * SEQ] = c0;
                    p[(size_t)(d + 1) * SEQ] = c1;
                }
            }
        }
    }
}

// ---------------- dots strip: q resident, loop over NB_PER k-tiles ---------
__global__ __launch_bounds__(256, 2) void dots_tc() {
    extern __shared__ float dynsm[];
    float* As = dynsm;                     // [2 chunks][128][PADC]  (q, resident)
    float* Bs = dynsm + 2 * 128 * PADC;    // [2 bufs][128][PADC]    (k, pipelined)
    __shared__ float sred[128][4];
    const int split = blockIdx.x, mb = blockIdx.y, bz = blockIdx.z;
    const float* Aq = g_q + (size_t)bz * SEQ * DH + (size_t)mb * 128 * DH;
    const float* Bk = g_k + (size_t)bz * SEQ * DH;

    const int tid = threadIdx.x, wid = tid >> 5, lane = tid & 31;
    const int g = lane >> 2, t = lane & 3;
    const int wr = wid >> 2, wc = wid & 3;
    const int arow = tid >> 1, ac0 = (tid & 1) * 16;
    const int lq = lane & 7, lt = lane >> 3;
    const uint32_t sa = smem_u32(As);
    const uint32_t sb = smem_u32(Bs);
    const uint32_t a0 = sa + (uint32_t)((wr * 64 + (lt & 1) * 8 + lq) * PADC + (lt >> 1) * 4) * 4u;
    const uint32_t b0 = sb + (uint32_t)((wc * 32 + (lt >> 1) * 8 + lq) * PADC + (lt & 1) * 4) * 4u;

    // load q (both chunks) once
#pragma unroll
    for (int ch = 0; ch < 2; ch++) {
        const float* ap = Aq + (size_t)arow * DH + ch * 32 + ac0;
        uint32_t da = sa + (uint32_t)(ch * 128 * PADC + arow * PADC + ac0) * 4u;
#pragma unroll
        for (int i = 0; i < 4; i++) CP_ASYNC16(da + i * 16, ap + i * 4);
    }
    CP_COMMIT();

    auto prefetch_k = [&](int gc, int buf) {
        int nb = split * NB_PER + (gc >> 1);
        int ch = gc & 1;
        const float* bp = Bk + ((size_t)nb * 128 + arow) * DH + ch * 32 + ac0;
        uint32_t db = sb + (uint32_t)(buf * 128 * PADC + arow * PADC + ac0) * 4u;
#pragma unroll
        for (int i = 0; i < 4; i++) CP_ASYNC16(db + i * 16, bp + i * 4);
        CP_COMMIT();
    };

    prefetch_k(0, 0);
    const int NCH = NB_PER * 2;
    float rs0[4] = {}, rs1[4] = {};
    float Cacc[64];
    for (int gc = 0; gc < NCH; gc++) {
        CP_WAIT0();
        __syncthreads();
        if (gc + 1 < NCH) prefetch_k(gc + 1, (gc + 1) & 1);
        if ((gc & 1) == 0) {
#pragma unroll
            for (int i = 0; i < 64; i++) Cacc[i] = 0.f;
        }
        const uint32_t ab = a0 + (uint32_t)(gc & 1) * (128 * PADC * 4);
        const uint32_t bb = b0 + (uint32_t)(gc & 1) * (128 * PADC * 4);
#pragma unroll
        for (int ks = 0; ks < 4; ks++) {
            uint32_t af[4][4], bf[2][4];
#pragma unroll
            for (int mi = 0; mi < 4; mi++)
                LDSM_X4(af[mi][0], af[mi][1], af[mi][2], af[mi][3],
                        ab + mi * (16 * PADC * 4) + ks * 32);
#pragma unroll
            for (int p = 0; p < 2; p++)
                LDSM_X4(bf[p][0], bf[p][1], bf[p][2], bf[p][3],
                        bb + p * (16 * PADC * 4) + ks * 32);
#pragma unroll
            for (int mi = 0; mi < 4; mi++)
#pragma unroll
                for (int ni = 0; ni < 4; ni++)
                    mma_tf32(&Cacc[(mi * 4 + ni) * 4], af[mi], &bf[ni >> 1][(ni & 1) * 2]);
        }
        if ((gc & 1) == 1) {
            int nb = split * NB_PER + (gc >> 1);
#pragma unroll
            for (int mi = 0; mi < 4; mi++) {
                int row0 = mb * 128 + wr * 64 + mi * 16 + g;
#pragma unroll
                for (int ni = 0; ni < 4; ni++) {
                    int col = nb * 128 + wc * 32 + ni * 8 + 2 * t;
                    float* cp = &Cacc[(mi * 4 + ni) * 4];
                    float e0 = __expf(cp[0] * SCALE), e1 = __expf(cp[1] * SCALE);
                    float e2 = __expf(cp[2] * SCALE), e3 = __expf(cp[3] * SCALE);
                    rs0[mi] += e0 + e1; rs1[mi] += e2 + e3;
                    *(float2*)(g_attn + (size_t)bz * NN + (size_t)row0 * SEQ + col)
                        = make_float2(e0, e1);
                    *(float2*)(g_attn + (size_t)bz * NN + (size_t)(row0 + 8) * SEQ + col)
                        = make_float2(e2, e3);
                }
            }
        }
    }
#pragma unroll
    for (int mi = 0; mi < 4; mi++) {
#pragma unroll
        for (int o = 1; o < 4; o <<= 1) {
            rs0[mi] += __shfl_xor_sync(0xffffffffu, rs0[mi], o);
            rs1[mi] += __shfl_xor_sync(0xffffffffu, rs1[mi], o);
        }
        if (t == 0) {
            int rl = wr * 64 + mi * 16 + g;
            sred[rl][wc] = rs0[mi];
            sred[rl + 8][wc] = rs1[mi];
        }
    }
    __syncthreads();
    if (tid < 128) {
        float s = sred[tid][0] + sred[tid][1] + sred[tid][2] + sred[tid][3];
        g_psum[((size_t)bz * SEQ + mb * 128 + tid) * NSPLIT + split] = s;
    }
}

// ---------------- head-mix (float4): one block == one (batch,row) ----------
__global__ __launch_bounds__(256) void mix_kernel() {
    __shared__ float Ms[HEADS * HEADS];
    __shared__ float ri[HEADS];
    const int blk = blockIdx.x;           // 0..ROWS-1
    const int b = blk >> 10;
    const int row = blk & 1023;
    const int tid = threadIdx.x;
    if (tid < HEADS * HEADS) Ms[tid] = g_M[tid];
    if (tid < HEADS) {
        const float* ps = g_psum + ((size_t)(b * HEADS + tid) * SEQ + row) * NSPLIT;
        float s = 0.f;
#pragma unroll
        for (int i = 0; i < NSPLIT; i++) s += ps[i];
        ri[tid] = 1.f / s;
    }
    __syncthreads();
    const size_t base = (size_t)b * HEADS * NN + (size_t)row * SEQ + tid * 4;
    float4 a[HEADS];
#pragma unroll
    for (int j = 0; j < HEADS; j++) {
        float4 v = *(const float4*)(g_attn + base + (size_t)j * NN);
        float r = ri[j];
        a[j] = make_float4(v.x * r, v.y * r, v.z * r, v.w * r);
    }
#pragma unroll
    for (int h = 0; h < HEADS; h++) {
        float4 s = make_float4(0.f, 0.f, 0.f, 0.f);
#pragma unroll
        for (int j = 0; j < HEADS; j++) {
            float m = Ms[h * HEADS + j];
            s.x += m * a[j].x; s.y += m * a[j].y;
            s.z += m * a[j].z; s.w += m * a[j].w;
        }
        float4 o = make_float4(to_tf32(a[h].x + fmaxf(s.x, 0.f)),
                               to_tf32(a[h].y + fmaxf(s.y, 0.f)),
                               to_tf32(a[h].z + fmaxf(s.z, 0.f)),
                               to_tf32(a[h].w + fmaxf(s.w, 0.f)));
        *(float4*)(g_P + base + (size_t)h * NN) = o;
    }
}

// ---------------- AV split-K: Opart[n,d] = P[n,sp-half] @ Vt[d,sp-half]^T --
__global__ __launch_bounds__(256, 3) void av_tc() {
    extern __shared__ float dynsm[];
    float* As = dynsm;
    float* Bs = dynsm + 2 * 128 * PADC;
    int mb = blockIdx.x, bz = blockIdx.y, sp = blockIdx.z;
    const int koff = sp * (SEQ / KSPLIT_AV);
    float Cacc[32] = {};
    gemm_pipe<64>(Cacc,
                  g_P + (size_t)bz * NN + (size_t)mb * 128 * SEQ + koff, SEQ,
                  g_vt + (size_t)bz * DH * SEQ + koff, SEQ,
                  SEQ / KSPLIT_AV, As, Bs);

    const int lane = threadIdx.x & 31, wid = threadIdx.x >> 5;
    const int g = lane >> 2, t = lane & 3;
    const int wr = wid >> 1, wc = wid & 1;
    int b = bz / HEADS, h = bz % HEADS;
    float* Od = sp ? g_Ob : g_Oa;
#pragma unroll
    for (int mi = 0; mi < 2; mi++) {
        int n0 = mb * 128 + wr * 32 + mi * 16 + g;
#pragma unroll
        for (int ni = 0; ni < 4; ni++) {
            int d = wc * 32 + ni * 8 + 2 * t;
            float* cp = &Cacc[(mi * 4 + ni) * 4];
            *(float2*)(Od + (size_t)(b * SEQ + n0) * INNER + h * DH + d)
                = make_float2(cp[0], cp[1]);
            *(float2*)(Od + (size_t)(b * SEQ + n0 + 8) * INNER + h * DH + d)
                = make_float2(cp[2], cp[3]);
        }
    }
}

// ---------------- O = tf32(Oa + Ob) ----------------------------------------
__global__ __launch_bounds__(256) void o_add() {
    int i = blockIdx.x * 256 + threadIdx.x;   // float4 index
    float4 a = ((const float4*)g_Oa)[i];
    float4 b = ((const float4*)g_Ob)[i];
    float4 o = make_float4(to_tf32(a.x + b.x), to_tf32(a.y + b.y),
                           to_tf32(a.z + b.z), to_tf32(a.w + b.w));
    ((float4*)g_O)[i] = o;
}

// ---------------- out projection (BN=64 tiles, 3 CTAs/SM) ------------------
__global__ __launch_bounds__(256, 3) void proj_tc(const float* __restrict__ bias,
                                                  float* __restrict__ out) {
    extern __shared__ float dynsm[];
    float* As = dynsm;
    float* Bs = dynsm + 2 * 128 * PADC;
    int nb = blockIdx.x, mb = blockIdx.y;
    float Cacc[32] = {};
    gemm_pipe<64>(Cacc, g_O + (size_t)mb * 128 * INNER, INNER,
                  g_wo + (size_t)nb * 64 * INNER, INNER, INNER, As, Bs);

    const int lane = threadIdx.x & 31, wid = threadIdx.x >> 5;
    const int g = lane >> 2, t = lane & 3;
    const int wr = wid >> 1, wc = wid & 1;
#pragma unroll
    for (int mi = 0; mi < 2; mi++) {
        int gi = mb * 128 + wr * 32 + mi * 16 + g;
#pragma unroll
        for (int ni = 0; ni < 4; ni++) {
            int j = nb * 64 + wc * 32 + ni * 8 + 2 * t;
            float b0 = bias[j], b1 = bias[j + 1];
            float* cp = &Cacc[(mi * 4 + ni) * 4];
            *(float2*)(out + (size_t)gi * DIM + j) = make_float2(cp[0] + b0, cp[1] + b1);
            *(float2*)(out + (size_t)(gi + 8) * DIM + j) = make_float2(cp[2] + b0, cp[3] + b1);
        }
    }
}

// ---------------- launcher -------------------------------------------------
extern "C" void kernel_launch(void* const* d_in, const int* in_sizes, int n_in,
                              void* d_out, int out_size) {
    const float* x     = (const float*)d_in[0];
    const float* ln_g  = (const float*)d_in[1];
    const float* ln_b  = (const float*)d_in[2];
    const float* w_qkv = (const float*)d_in[3];
    const float* w_out = (const float*)d_in[4];
    const float* b_out = (const float*)d_in[5];
    const float* theta = (const float*)d_in[6];
    const float* gnn_w = (const float*)d_in[7];
    float* out = (float*)d_out;

    cudaFuncSetAttribute(qkv_tc,  cudaFuncAttributeMaxDynamicSharedMemorySize, SMEM64);
    cudaFuncSetAttribute(dots_tc, cudaFuncAttributeMaxDynamicSharedMemorySize, SMEM128);
    cudaFuncSetAttribute(av_tc,   cudaFuncAttributeMaxDynamicSharedMemorySize, SMEM64);
    cudaFuncSetAttribute(proj_tc, cudaFuncAttributeMaxDynamicSharedMemorySize, SMEM64);

    ln_kernel<<<ROWS, 256>>>(x, ln_g, ln_b);
    m_kernel<<<1, 160>>>(theta, gnn_w);
    round_w2<<<(WQ4 + WO4 + 255) / 256, 256>>>(w_qkv, w_out);
    qkv_tc<<<dim3(36, 16), 256, SMEM64>>>();
    dots_tc<<<dim3(NSPLIT, 8, BH), 256, SMEM128>>>();
    mix_kernel<<<BATCH * SEQ, 256>>>();
    av_tc<<<dim3(8, BH, KSPLIT_AV), 256, SMEM64>>>();
    o_add<<<(ROWS * INNER / 4) / 256, 256>>>();
    proj_tc<<<dim3(12, 16), 256, SMEM64>>>(b_out, out);
}

// round 15
// speedup vs baseline: 1.0558x; 1.0558x over previous
#include <cuda_runtime.h>
#include <cstdint>

#define DIM 768
#define HEADS 12
#define DH 64
#define INNER 768
#define BATCH 2
#define SEQ 1024
#define ROWS (BATCH*SEQ)      // 2048
#define NN (SEQ*SEQ)          // 1048576
#define BH (BATCH*HEADS)      // 24
#define SCALE 0.125f
#define LN_EPS 1e-5f
#define PADC 36               // floats per 32-float chunk row (144B, 16B mult)
#define NSPLIT 4
#define NB_PER (8/NSPLIT)     // k-tiles per dots block
#define KSPLIT_AV 2

// ---------------- scratch (device globals; no allocation allowed) ----------
__device__ float g_xn[ROWS*DIM];               // tf32-rounded
__device__ float g_wq[3*INNER*DIM];            // tf32-rounded w_qkv
__device__ float g_wo[DIM*INNER];              // tf32-rounded w_out
__device__ float g_q[BH*SEQ*DH];               // tf32-rounded
__device__ float g_k[BH*SEQ*DH];               // tf32-rounded
__device__ float g_vt[BH*DH*SEQ];              // tf32-rounded, [bh][d][n]
__device__ float g_attn[(size_t)BH*NN];        // full fp32 exp(logits)
__device__ float g_P[(size_t)BH*NN];           // tf32-rounded
__device__ float g_psum[BH*SEQ*NSPLIT];
__device__ float g_Oa[ROWS*INNER];             // av partial (K first half)
__device__ float g_Ob[ROWS*INNER];             // av partial (K second half)
__device__ float g_O[ROWS*INNER];              // summed, tf32-rounded
__device__ float g_M[HEADS*HEADS];

// ---------------- helpers --------------------------------------------------
__device__ __forceinline__ uint32_t smem_u32(const void* p) {
    uint32_t a;
    asm("{ .reg .u64 t; cvta.to.shared.u64 t, %1; cvt.u32.u64 %0, t; }"
        : "=r"(a) : "l"(p));
    return a;
}
__device__ __forceinline__ float to_tf32(float x) {
    float y;
    asm("cvt.rna.tf32.f32 %0, %1;" : "=f"(y) : "f"(x));
    return y;
}
__device__ __forceinline__ void mma_tf32(float* c, const uint32_t* a, const uint32_t* b) {
    asm volatile(
        "mma.sync.aligned.m16n8k8.row.col.f32.tf32.tf32.f32 "
        "{%0,%1,%2,%3}, {%4,%5,%6,%7}, {%8,%9}, {%0,%1,%2,%3};"
        : "+f"(c[0]), "+f"(c[1]), "+f"(c[2]), "+f"(c[3])
        : "r"(a[0]), "r"(a[1]), "r"(a[2]), "r"(a[3]), "r"(b[0]), "r"(b[1]));
}
#define LDSM_X4(r0, r1, r2, r3, addr) \
    asm volatile("ldmatrix.sync.aligned.m8n8.x4.shared.b16 {%0,%1,%2,%3}, [%4];" \
        : "=r"(r0), "=r"(r1), "=r"(r2), "=r"(r3) : "r"(addr))
#define CP_ASYNC16(dst, src) \
    asm volatile("cp.async.cg.shared.global [%0], [%1], 16;" \
        :: "r"(dst), "l"(src) : "memory")
#define CP_COMMIT()  asm volatile("cp.async.commit_group;" ::: "memory")
#define CP_WAIT1()   asm volatile("cp.async.wait_group 1;" ::: "memory")
#define CP_WAIT0()   asm volatile("cp.async.wait_group 0;" ::: "memory")

// ---- pipelined tf32 mma core: D[128,BN]=A[128,K]@B[BN,K]^T ----------------
// ldmatrix fragment loads. STAGES-deep cp.async ring (2 or 3).
// Chunk c lives in buffer c%STAGES. Wait policy: keep STAGES-2 loads in
// flight in steady state; drain fully on the last chunk.
template<int BN, int STAGES>
__device__ __forceinline__ void gemm_pipe(float* Cacc,
                                          const float* __restrict__ A, int lda,
                                          const float* __restrict__ B, int ldb,
                                          int K, float* As, float* Bs) {
    constexpr int WC = BN / 32;
    constexpr int WR = 8 / WC;
    constexpr int WM = 128 / WR;
    constexpr int MT = WM / 16;
    constexpr int BTPR = 256 / BN;
    constexpr int BSEG = 32 / BTPR;
    constexpr int PF = STAGES - 1;

    const int tid = threadIdx.x, wid = tid >> 5, lane = tid & 31;
    const int wr = wid / WC, wc = wid % WC;
    const int wm0 = wr * WM, wn0 = wc * 32;
    const int arow = tid >> 1, ac0 = (tid & 1) * 16;
    const int brow = tid / BTPR, bc0 = (tid % BTPR) * BSEG;
    const int lq = lane & 7, lt = lane >> 3;

    const uint32_t sa = smem_u32(As);
    const uint32_t sb = smem_u32(Bs);
    const uint32_t a0 = sa + (uint32_t)((wm0 + (lt & 1) * 8 + lq) * PADC + (lt >> 1) * 4) * 4u;
    const uint32_t b0 = sb + (uint32_t)((wn0 + (lt >> 1) * 8 + lq) * PADC + (lt & 1) * 4) * 4u;
    const int nch = K >> 5;

    auto prefetch = [&](int c, int buf) {
        const float* ap = A + (size_t)arow * lda + c * 32 + ac0;
        uint32_t da = sa + (uint32_t)(buf * 128 * PADC + arow * PADC + ac0) * 4u;
#pragma unroll
        for (int i = 0; i < 4; i++) CP_ASYNC16(da + i * 16, ap + i * 4);
        const float* bp = B + (size_t)brow * ldb + c * 32 + bc0;
        uint32_t db = sb + (uint32_t)(buf * BN * PADC + brow * PADC + bc0) * 4u;
#pragma unroll
        for (int i = 0; i < BSEG / 4; i++) CP_ASYNC16(db + i * 16, bp + i * 4);
        CP_COMMIT();
    };

    prefetch(0, 0);
    if (STAGES >= 3 && nch > 1) prefetch(1, 1);
    for (int c = 0; c < nch; c++) {
        if (STAGES >= 3 && c < nch - 1) CP_WAIT1(); else CP_WAIT0();
        __syncthreads();
        if (c + PF < nch) prefetch(c + PF, (c + PF) % STAGES);
        const uint32_t ab = a0 + (uint32_t)(c % STAGES) * (128 * PADC * 4);
        const uint32_t bb = b0 + (uint32_t)(c % STAGES) * (BN * PADC * 4);
#pragma unroll
        for (int ks = 0; ks < 4; ks++) {
            uint32_t af[MT][4], bf[2][4];
#pragma unroll
            for (int mi = 0; mi < MT; mi++)
                LDSM_X4(af[mi][0], af[mi][1], af[mi][2], af[mi][3],
                        ab + mi * (16 * PADC * 4) + ks * 32);
#pragma unroll
            for (int p = 0; p < 2; p++)
                LDSM_X4(bf[p][0], bf[p][1], bf[p][2], bf[p][3],
                        bb + p * (16 * PADC * 4) + ks * 32);
#pragma unroll
            for (int mi = 0; mi < MT; mi++)
#pragma unroll
                for (int ni = 0; ni < 4; ni++)
                    mma_tf32(&Cacc[(mi * 4 + ni) * 4], af[mi], &bf[ni >> 1][(ni & 1) * 2]);
        }
    }
    __syncthreads();
}

#define SMEM_QKV ((3*128 + 3*128) * PADC * 4)   // 110592 B (BN=128, 3 stages)
#define SMEM_DOTS ((2*128 + 3*128) * PADC * 4)  // 92160 B  (q resident + 3 k-bufs)
#define SMEM64  ((2*128 + 2*64)  * PADC * 4)    // 55296 B  (BN=64, 2 stages)

// ---------------- tf32 pre-round (both weight tensors, one launch) ---------
#define WQ4 ((3*INNER*DIM)/4)
#define WO4 ((DIM*INNER)/4)
__global__ __launch_bounds__(256) void round_w2(const float* __restrict__ wq,
                                                const float* __restrict__ wo) {
    int i = blockIdx.x * 256 + threadIdx.x;
    const float4* src;
    float4* dst;
    int j;
    if (i < WQ4) { src = (const float4*)wq; j = i;        dst = (float4*)g_wq; }
    else if (i < WQ4 + WO4) { src = (const float4*)wo; j = i - WQ4; dst = (float4*)g_wo; }
    else return;
    float4 v = src[j];
    v.x = to_tf32(v.x); v.y = to_tf32(v.y); v.z = to_tf32(v.z); v.w = to_tf32(v.w);
    dst[j] = v;
}

// ---------------- LayerNorm (stores tf32-rounded xn) -----------------------
__global__ __launch_bounds__(256) void ln_kernel(const float* __restrict__ x,
                                                 const float* __restrict__ gam,
                                                 const float* __restrict__ bet) {
    int row = blockIdx.x;
    const float* xr = x + (size_t)row * DIM;
    float vals[3];
    float s = 0.f, s2 = 0.f;
#pragma unroll
    for (int i = 0; i < 3; i++) {
        float v = xr[threadIdx.x + i * 256];
        vals[i] = v; s += v; s2 += v * v;
    }
    __shared__ float sh1[32], sh2[32];
#pragma unroll
    for (int o = 16; o > 0; o >>= 1) {
        s  += __shfl_down_sync(0xffffffffu, s,  o);
        s2 += __shfl_down_sync(0xffffffffu, s2, o);
    }
    int lane = threadIdx.x & 31, wid = threadIdx.x >> 5;
    if (lane == 0) { sh1[wid] = s; sh2[wid] = s2; }
    __syncthreads();
    if (wid == 0) {
        s  = (lane < 8) ? sh1[lane] : 0.f;
        s2 = (lane < 8) ? sh2[lane] : 0.f;
#pragma unroll
        for (int o = 4; o > 0; o >>= 1) {
            s  += __shfl_down_sync(0xffffffffu, s,  o);
            s2 += __shfl_down_sync(0xffffffffu, s2, o);
        }
        if (lane == 0) { sh1[0] = s; sh2[0] = s2; }
    }
    __syncthreads();
    float mean = sh1[0] * (1.f / DIM);
    float var  = sh2[0] * (1.f / DIM) - mean * mean;
    float rstd = rsqrtf(var + LN_EPS);
#pragma unroll
    for (int i = 0; i < 3; i++) {
        int c = threadIdx.x + i * 256;
        g_xn[(size_t)row * DIM + c] = to_tf32((vals[i] - mean) * rstd * gam[c] + bet[c]);
    }
}

// ---------------- M = (-0.5*theta) @ gnn_w ---------------------------------
__global__ void m_kernel(const float* __restrict__ theta, const float* __restrict__ w) {
    int t = threadIdx.x;
    if (t < HEADS * HEADS) {
        int i = t / HEADS, m = t % HEADS;
        float s = 0.f;
#pragma unroll
        for (int j = 0; j < HEADS; j++)
            s += (-0.5f * theta[i * HEADS + j]) * w[j * HEADS + m];
        g_M[t] = s;
    }
}

// ---------------- QKV: BN=128, 3-stage pipeline, scatter to heads ----------
__global__ __launch_bounds__(256, 2) void qkv_tc() {
    extern __shared__ float dynsm[];
    float* As = dynsm;
    float* Bs = dynsm + 3 * 128 * PADC;
    int nb = blockIdx.x, mb = blockIdx.y;
    float Cacc[64] = {};
    gemm_pipe<128, 3>(Cacc, g_xn + (size_t)mb * 128 * DIM, DIM,
                      g_wq + (size_t)nb * 128 * DIM, DIM, DIM, As, Bs);

    const int lane = threadIdx.x & 31, wid = threadIdx.x >> 5;
    const int g = lane >> 2, t = lane & 3;
    const int wr = wid >> 2, wc = wid & 3;
#pragma unroll
    for (int mi = 0; mi < 4; mi++) {
        int gi0 = mb * 128 + wr * 64 + mi * 16 + g;
#pragma unroll
        for (int ni = 0; ni < 4; ni++) {
            int j = nb * 128 + wc * 32 + ni * 8 + 2 * t;
            int which = j / INNER;
            int rc = j - which * INNER;
            int h = rc >> 6, d = rc & 63;
            const float* cp = &Cacc[(mi * 4 + ni) * 4];
#pragma unroll
            for (int half = 0; half < 2; half++) {
                int gi = gi0 + half * 8;
                int b = gi >> 10, n = gi & 1023;
                float c0 = to_tf32(cp[half * 2]), c1 = to_tf32(cp[half * 2 + 1]);
                if (which < 2) {
                    float* dst = (which == 0) ? g_q : g_k;
                    *(float2*)(dst + ((size_t)(b * HEADS + h) * SEQ + n) * DH + d)
                        = make_float2(c0, c1);
                } else {
                    float* p = g_vt + (size_t)(b * HEADS + h) * DH * SEQ + n;
                    p[(size_t)d * SEQ] = c0;
                    p[(size_t)(d + 1) * SEQ] = c1;
                }
            }
        }
    }
}

// ---------------- dots strip: q resident, 3-deep k ring --------------------
__global__ __launch_bounds__(256, 2) void dots_tc() {
    extern __shared__ float dynsm[];
    float* As = dynsm;                     // [2 chunks][128][PADC]  (q, resident)
    float* Bs = dynsm + 2 * 128 * PADC;    // [3 bufs][128][PADC]    (k ring)
    __shared__ float sred[128][4];
    const int split = blockIdx.x, mb = blockIdx.y, bz = blockIdx.z;
    const float* Aq = g_q + (size_t)bz * SEQ * DH + (size_t)mb * 128 * DH;
    const float* Bk = g_k + (size_t)bz * SEQ * DH;

    const int tid = threadIdx.x, wid = tid >> 5, lane = tid & 31;
    const int g = lane >> 2, t = lane & 3;
    const int wr = wid >> 2, wc = wid & 3;
    const int arow = tid >> 1, ac0 = (tid & 1) * 16;
    const int lq = lane & 7, lt = lane >> 3;
    const uint32_t sa = smem_u32(As);
    const uint32_t sb = smem_u32(Bs);
    const uint32_t a0 = sa + (uint32_t)((wr * 64 + (lt & 1) * 8 + lq) * PADC + (lt >> 1) * 4) * 4u;
    const uint32_t b0 = sb + (uint32_t)((wc * 32 + (lt >> 1) * 8 + lq) * PADC + (lt & 1) * 4) * 4u;

    // load q (both chunks) once — one group
#pragma unroll
    for (int ch = 0; ch < 2; ch++) {
        const float* ap = Aq + (size_t)arow * DH + ch * 32 + ac0;
        uint32_t da = sa + (uint32_t)(ch * 128 * PADC + arow * PADC + ac0) * 4u;
#pragma unroll
        for (int i = 0; i < 4; i++) CP_ASYNC16(da + i * 16, ap + i * 4);
    }
    CP_COMMIT();

    auto prefetch_k = [&](int gc) {
        int nb = split * NB_PER + (gc >> 1);
        int ch = gc & 1;
        const float* bp = Bk + ((size_t)nb * 128 + arow) * DH + ch * 32 + ac0;
        uint32_t db = sb + (uint32_t)((gc % 3) * 128 * PADC + arow * PADC + ac0) * 4u;
#pragma unroll
        for (int i = 0; i < 4; i++) CP_ASYNC16(db + i * 16, bp + i * 4);
        CP_COMMIT();
    };

    const int NCH = NB_PER * 2;
    prefetch_k(0);
    if (NCH > 1) prefetch_k(1);
    float rs0[4] = {}, rs1[4] = {};
    float Cacc[64];
    for (int gc = 0; gc < NCH; gc++) {
        if (gc < NCH - 1) CP_WAIT1(); else CP_WAIT0();
        __syncthreads();
        if (gc + 2 < NCH) prefetch_k(gc + 2);
        if ((gc & 1) == 0) {
#pragma unroll
            for (int i = 0; i < 64; i++) Cacc[i] = 0.f;
        }
        const uint32_t ab = a0 + (uint32_t)(gc & 1) * (128 * PADC * 4);
        const uint32_t bb = b0 + (uint32_t)(gc % 3) * (128 * PADC * 4);
#pragma unroll
        for (int ks = 0; ks < 4; ks++) {
            uint32_t af[4][4], bf[2][4];
#pragma unroll
            for (int mi = 0; mi < 4; mi++)
                LDSM_X4(af[mi][0], af[mi][1], af[mi][2], af[mi][3],
                        ab + mi * (16 * PADC * 4) + ks * 32);
#pragma unroll
            for (int p = 0; p < 2; p++)
                LDSM_X4(bf[p][0], bf[p][1], bf[p][2], bf[p][3],
                        bb + p * (16 * PADC * 4) + ks * 32);
#pragma unroll
            for (int mi = 0; mi < 4; mi++)
#pragma unroll
                for (int ni = 0; ni < 4; ni++)
                    mma_tf32(&Cacc[(mi * 4 + ni) * 4], af[mi], &bf[ni >> 1][(ni & 1) * 2]);
        }
        if ((gc & 1) == 1) {
            int nb = split * NB_PER + (gc >> 1);
#pragma unroll
            for (int mi = 0; mi < 4; mi++) {
                int row0 = mb * 128 + wr * 64 + mi * 16 + g;
#pragma unroll
                for (int ni = 0; ni < 4; ni++) {
                    int col = nb * 128 + wc * 32 + ni * 8 + 2 * t;
                    float* cp = &Cacc[(mi * 4 + ni) * 4];
                    float e0 = __expf(cp[0] * SCALE), e1 = __expf(cp[1] * SCALE);
                    float e2 = __expf(cp[2] * SCALE), e3 = __expf(cp[3] * SCALE);
                    rs0[mi] += e0 + e1; rs1[mi] += e2 + e3;
                    *(float2*)(g_attn + (size_t)bz * NN + (size_t)row0 * SEQ + col)
                        = make_float2(e0, e1);
                    *(float2*)(g_attn + (size_t)bz * NN + (size_t)(row0 + 8) * SEQ + col)
                        = make_float2(e2, e3);
                }
            }
        }
    }
#pragma unroll
    for (int mi = 0; mi < 4; mi++) {
#pragma unroll
        for (int o = 1; o < 4; o <<= 1) {
            rs0[mi] += __shfl_xor_sync(0xffffffffu, rs0[mi], o);
            rs1[mi] += __shfl_xor_sync(0xffffffffu, rs1[mi], o);
        }
        if (t == 0) {
            int rl = wr * 64 + mi * 16 + g;
            sred[rl][wc] = rs0[mi];
            sred[rl + 8][wc] = rs1[mi];
        }
    }
    __syncthreads();
    if (tid < 128) {
        float s = sred[tid][0] + sred[tid][1] + sred[tid][2] + sred[tid][3];
        g_psum[((size_t)bz * SEQ + mb * 128 + tid) * NSPLIT + split] = s;
    }
}

// ---------------- head-mix (float4): one block == one (batch,row) ----------
__global__ __launch_bounds__(256) void mix_kernel() {
    __shared__ float Ms[HEADS * HEADS];
    __shared__ float ri[HEADS];
    const int blk = blockIdx.x;           // 0..ROWS-1
    const int b = blk >> 10;
    const int row = blk & 1023;
    const int tid = threadIdx.x;
    if (tid < HEADS * HEADS) Ms[tid] = g_M[tid];
    if (tid < HEADS) {
        const float* ps = g_psum + ((size_t)(b * HEADS + tid) * SEQ + row) * NSPLIT;
        float s = 0.f;
#pragma unroll
        for (int i = 0; i < NSPLIT; i++) s += ps[i];
        ri[tid] = 1.f / s;
    }
    __syncthreads();
    const size_t base = (size_t)b * HEADS * NN + (size_t)row * SEQ + tid * 4;
    float4 a[HEADS];
#pragma unroll
    for (int j = 0; j < HEADS; j++) {
        float4 v = *(const float4*)(g_attn + base + (size_t)j * NN);
        float r = ri[j];
        a[j] = make_float4(v.x * r, v.y * r, v.z * r, v.w * r);
    }
#pragma unroll
    for (int h = 0; h < HEADS; h++) {
        float4 s = make_float4(0.f, 0.f, 0.f, 0.f);
#pragma unroll
        for (int j = 0; j < HEADS; j++) {
            float m = Ms[h * HEADS + j];
            s.x += m * a[j].x; s.y += m * a[j].y;
            s.z += m * a[j].z; s.w += m * a[j].w;
        }
        float4 o = make_float4(to_tf32(a[h].x + fmaxf(s.x, 0.f)),
                               to_tf32(a[h].y + fmaxf(s.y, 0.f)),
                               to_tf32(a[h].z + fmaxf(s.z, 0.f)),
                               to_tf32(a[h].w + fmaxf(s.w, 0.f)));
        *(float4*)(g_P + base + (size_t)h * NN) = o;
    }
}

// ---------------- AV split-K: Opart[n,d] = P[n,sp-half] @ Vt[d,sp-half]^T --
__global__ __launch_bounds__(256, 3) void av_tc() {
    extern __shared__ float dynsm[];
    float* As = dynsm;
    float* Bs = dynsm + 2 * 128 * PADC;
    int mb = blockIdx.x, bz = blockIdx.y, sp = blockIdx.z;
    const int koff = sp * (SEQ / KSPLIT_AV);
    float Cacc[32] = {};
    gemm_pipe<64, 2>(Cacc,
                     g_P + (size_t)bz * NN + (size_t)mb * 128 * SEQ + koff, SEQ,
                     g_vt + (size_t)bz * DH * SEQ + koff, SEQ,
                     SEQ / KSPLIT_AV, As, Bs);

    const int lane = threadIdx.x & 31, wid = threadIdx.x >> 5;
    const int g = lane >> 2, t = lane & 3;
    const int wr = wid >> 1, wc = wid & 1;
    int b = bz / HEADS, h = bz % HEADS;
    float* Od = sp ? g_Ob : g_Oa;
#pragma unroll
    for (int mi = 0; mi < 2; mi++) {
        int n0 = mb * 128 + wr * 32 + mi * 16 + g;
#pragma unroll
        for (int ni = 0; ni < 4; ni++) {
            int d = wc * 32 + ni * 8 + 2 * t;
            float* cp = &Cacc[(mi * 4 + ni) * 4];
            *(float2*)(Od + (size_t)(b * SEQ + n0) * INNER + h * DH + d)
                = make_float2(cp[0], cp[1]);
            *(float2*)(Od + (size_t)(b * SEQ + n0 + 8) * INNER + h * DH + d)
                = make_float2(cp[2], cp[3]);
        }
    }
}

// ---------------- O = tf32(Oa + Ob) ----------------------------------------
__global__ __launch_bounds__(256) void o_add() {
    int i = blockIdx.x * 256 + threadIdx.x;   // float4 index
    float4 a = ((const float4*)g_Oa)[i];
    float4 b = ((const float4*)g_Ob)[i];
    float4 o = make_float4(to_tf32(a.x + b.x), to_tf32(a.y + b.y),
                           to_tf32(a.z + b.z), to_tf32(a.w + b.w));
    ((float4*)g_O)[i] = o;
}

// ---------------- out projection (BN=64 tiles, 3 CTAs/SM) ------------------
__global__ __launch_bounds__(256, 3) void proj_tc(const float* __restrict__ bias,
                                                  float* __restrict__ out) {
    extern __shared__ float dynsm[];
    float* As = dynsm;
    float* Bs = dynsm + 2 * 128 * PADC;
    int nb = blockIdx.x, mb = blockIdx.y;
    float Cacc[32] = {};
    gemm_pipe<64, 2>(Cacc, g_O + (size_t)mb * 128 * INNER, INNER,
                     g_wo + (size_t)nb * 64 * INNER, INNER, INNER, As, Bs);

    const int lane = threadIdx.x & 31, wid = threadIdx.x >> 5;
    const int g = lane >> 2, t = lane & 3;
    const int wr = wid >> 1, wc = wid & 1;
#pragma unroll
    for (int mi = 0; mi < 2; mi++) {
        int gi = mb * 128 + wr * 32 + mi * 16 + g;
#pragma unroll
        for (int ni = 0; ni < 4; ni++) {
            int j = nb * 64 + wc * 32 + ni * 8 + 2 * t;
            float b0 = bias[j], b1 = bias[j + 1];
            float* cp = &Cacc[(mi * 4 + ni) * 4];
            *(float2*)(out + (size_t)gi * DIM + j) = make_float2(cp[0] + b0, cp[1] + b1);
            *(float2*)(out + (size_t)(gi + 8) * DIM + j) = make_float2(cp[2] + b0, cp[3] + b1);
        }
    }
}

// ---------------- launcher -------------------------------------------------
extern "C" void kernel_launch(void* const* d_in, const int* in_sizes, int n_in,
                              void* d_out, int out_size) {
    const float* x     = (const float*)d_in[0];
    const float* ln_g  = (const float*)d_in[1];
    const float* ln_b  = (const float*)d_in[2];
    const float* w_qkv = (const float*)d_in[3];
    const float* w_out = (const float*)d_in[4];
    const float* b_out = (const float*)d_in[5];
    const float* theta = (const float*)d_in[6];
    const float* gnn_w = (const float*)d_in[7];
    float* out = (float*)d_out;

    cudaFuncSetAttribute(qkv_tc,  cudaFuncAttributeMaxDynamicSharedMemorySize, SMEM_QKV);
    cudaFuncSetAttribute(dots_tc, cudaFuncAttributeMaxDynamicSharedMemorySize, SMEM_DOTS);
    cudaFuncSetAttribute(av_tc,   cudaFuncAttributeMaxDynamicSharedMemorySize, SMEM64);
    cudaFuncSetAttribute(proj_tc, cudaFuncAttributeMaxDynamicSharedMemorySize, SMEM64);

    ln_kernel<<<ROWS, 256>>>(x, ln_g, ln_b);
    m_kernel<<<1, 160>>>(theta, gnn_w);
    round_w2<<<(WQ4 + WO4 + 255) / 256, 256>>>(w_qkv, w_out);
    qkv_tc<<<dim3(18, 16), 256, SMEM_QKV>>>();
    dots_tc<<<dim3(NSPLIT, 8, BH), 256, SMEM_DOTS>>>();
    mix_kernel<<<BATCH * SEQ, 256>>>();
    av_tc<<<dim3(8, BH, KSPLIT_AV), 256, SMEM64>>>();
    o_add<<<(ROWS * INNER / 4) / 256, 256>>>();
    proj_tc<<<dim3(12, 16), 256, SMEM64>>>(b_out, out);
}

// round 16
// speedup vs baseline: 1.0780x; 1.0210x over previous
#include <cuda_runtime.h>
#include <cstdint>

#define DIM 768
#define HEADS 12
#define DH 64
#define INNER 768
#define BATCH 2
#define SEQ 1024
#define ROWS (BATCH*SEQ)      // 2048
#define NN (SEQ*SEQ)          // 1048576
#define BH (BATCH*HEADS)      // 24
#define SCALE 0.125f
#define LN_EPS 1e-5f
#define PADC 36               // floats per 32-float chunk row (144B, 16B mult)
#define NSPLIT 4
#define NB_PER (8/NSPLIT)     // k-tiles per dots block
#define KSPLIT_AV 2

// ---------------- scratch (device globals; no allocation allowed) ----------
__device__ float g_xn[ROWS*DIM];               // tf32-rounded
__device__ float g_wq[3*INNER*DIM];            // tf32-rounded w_qkv
__device__ float g_wo[DIM*INNER];              // tf32-rounded w_out
__device__ float g_q[BH*SEQ*DH];               // tf32-rounded
__device__ float g_k[BH*SEQ*DH];               // tf32-rounded
__device__ float g_vt[BH*DH*SEQ];              // tf32-rounded, [bh][d][n]
__device__ float g_attn[(size_t)BH*NN];        // full fp32 exp(logits)
__device__ float g_P[(size_t)BH*NN];           // tf32-rounded
__device__ float g_psum[BH*SEQ*NSPLIT];
__device__ float g_O[ROWS*INNER];              // red.global accumulated
__device__ float g_M[HEADS*HEADS];

// ---------------- helpers --------------------------------------------------
__device__ __forceinline__ uint32_t smem_u32(const void* p) {
    uint32_t a;
    asm("{ .reg .u64 t; cvta.to.shared.u64 t, %1; cvt.u32.u64 %0, t; }"
        : "=r"(a) : "l"(p));
    return a;
}
__device__ __forceinline__ float to_tf32(float x) {
    float y;
    asm("cvt.rna.tf32.f32 %0, %1;" : "=f"(y) : "f"(x));
    return y;
}
__device__ __forceinline__ void mma_tf32(float* c, const uint32_t* a, const uint32_t* b) {
    asm volatile(
        "mma.sync.aligned.m16n8k8.row.col.f32.tf32.tf32.f32 "
        "{%0,%1,%2,%3}, {%4,%5,%6,%7}, {%8,%9}, {%0,%1,%2,%3};"
        : "+f"(c[0]), "+f"(c[1]), "+f"(c[2]), "+f"(c[3])
        : "r"(a[0]), "r"(a[1]), "r"(a[2]), "r"(a[3]), "r"(b[0]), "r"(b[1]));
}
#define LDSM_X4(r0, r1, r2, r3, addr) \
    asm volatile("ldmatrix.sync.aligned.m8n8.x4.shared.b16 {%0,%1,%2,%3}, [%4];" \
        : "=r"(r0), "=r"(r1), "=r"(r2), "=r"(r3) : "r"(addr))
#define CP_ASYNC16(dst, src) \
    asm volatile("cp.async.cg.shared.global [%0], [%1], 16;" \
        :: "r"(dst), "l"(src) : "memory")
#define CP_COMMIT()  asm volatile("cp.async.commit_group;" ::: "memory")
#define CP_WAIT1()   asm volatile("cp.async.wait_group 1;" ::: "memory")
#define CP_WAIT0()   asm volatile("cp.async.wait_group 0;" ::: "memory")
#define REDADD(addr, v) \
    asm volatile("red.global.add.f32 [%0], %1;" :: "l"(addr), "f"(v) : "memory")

// ---- pipelined tf32 mma core: D[128,BN]=A[128,K]@B[BN,K]^T ----------------
// ldmatrix fragment loads. STAGES-deep cp.async ring. CVTA: round A frags
// to tf32 after LDSM (for raw-fp32 A operands).
template<int BN, int STAGES, bool CVTA>
__device__ __forceinline__ void gemm_pipe(float* Cacc,
                                          const float* __restrict__ A, int lda,
                                          const float* __restrict__ B, int ldb,
                                          int K, float* As, float* Bs) {
    constexpr int WC = BN / 32;
    constexpr int WR = 8 / WC;
    constexpr int WM = 128 / WR;
    constexpr int MT = WM / 16;
    constexpr int BTPR = 256 / BN;
    constexpr int BSEG = 32 / BTPR;
    constexpr int PF = STAGES - 1;

    const int tid = threadIdx.x, wid = tid >> 5, lane = tid & 31;
    const int wr = wid / WC, wc = wid % WC;
    const int wm0 = wr * WM, wn0 = wc * 32;
    const int arow = tid >> 1, ac0 = (tid & 1) * 16;
    const int brow = tid / BTPR, bc0 = (tid % BTPR) * BSEG;
    const int lq = lane & 7, lt = lane >> 3;

    const uint32_t sa = smem_u32(As);
    const uint32_t sb = smem_u32(Bs);
    const uint32_t a0 = sa + (uint32_t)((wm0 + (lt & 1) * 8 + lq) * PADC + (lt >> 1) * 4) * 4u;
    const uint32_t b0 = sb + (uint32_t)((wn0 + (lt >> 1) * 8 + lq) * PADC + (lt & 1) * 4) * 4u;
    const int nch = K >> 5;

    auto prefetch = [&](int c, int buf) {
        const float* ap = A + (size_t)arow * lda + c * 32 + ac0;
        uint32_t da = sa + (uint32_t)(buf * 128 * PADC + arow * PADC + ac0) * 4u;
#pragma unroll
        for (int i = 0; i < 4; i++) CP_ASYNC16(da + i * 16, ap + i * 4);
        const float* bp = B + (size_t)brow * ldb + c * 32 + bc0;
        uint32_t db = sb + (uint32_t)(buf * BN * PADC + brow * PADC + bc0) * 4u;
#pragma unroll
        for (int i = 0; i < BSEG / 4; i++) CP_ASYNC16(db + i * 16, bp + i * 4);
        CP_COMMIT();
    };

    prefetch(0, 0);
    if (STAGES >= 3 && nch > 1) prefetch(1, 1);
    for (int c = 0; c < nch; c++) {
        if (STAGES >= 3 && c < nch - 1) CP_WAIT1(); else CP_WAIT0();
        __syncthreads();
        if (c + PF < nch) prefetch(c + PF, (c + PF) % STAGES);
        const uint32_t ab = a0 + (uint32_t)(c % STAGES) * (128 * PADC * 4);
        const uint32_t bb = b0 + (uint32_t)(c % STAGES) * (BN * PADC * 4);
#pragma unroll
        for (int ks = 0; ks < 4; ks++) {
            uint32_t af[MT][4], bf[2][4];
#pragma unroll
            for (int mi = 0; mi < MT; mi++) {
                LDSM_X4(af[mi][0], af[mi][1], af[mi][2], af[mi][3],
                        ab + mi * (16 * PADC * 4) + ks * 32);
                if (CVTA) {
#pragma unroll
                    for (int r = 0; r < 4; r++)
                        af[mi][r] = __float_as_uint(to_tf32(__uint_as_float(af[mi][r])));
                }
            }
#pragma unroll
            for (int p = 0; p < 2; p++)
                LDSM_X4(bf[p][0], bf[p][1], bf[p][2], bf[p][3],
                        bb + p * (16 * PADC * 4) + ks * 32);
#pragma unroll
            for (int mi = 0; mi < MT; mi++)
#pragma unroll
                for (int ni = 0; ni < 4; ni++)
                    mma_tf32(&Cacc[(mi * 4 + ni) * 4], af[mi], &bf[ni >> 1][(ni & 1) * 2]);
        }
    }
    __syncthreads();
}

#define SMEM128 ((2*128 + 2*128) * PADC * 4)    // 73728 B (BN=128, 2 stages)
#define SMEM_DOTS ((2*128 + 3*128) * PADC * 4)  // 92160 B (q resident + 3 k-bufs)
#define SMEM64  ((2*128 + 2*64)  * PADC * 4)    // 55296 B (BN=64, 2 stages)

// ---------------- prep: ln + weight rounding + M, one launch ---------------
#define WQ4 ((3*INNER*DIM)/4)
#define WO4 ((DIM*INNER)/4)
#define RW_BLOCKS ((WQ4 + WO4 + 255) / 256)
__global__ __launch_bounds__(256) void prep_kernel(
        const float* __restrict__ x, const float* __restrict__ gam,
        const float* __restrict__ bet, const float* __restrict__ wq,
        const float* __restrict__ wo, const float* __restrict__ theta,
        const float* __restrict__ w) {
    int blk = blockIdx.x;
    if (blk < ROWS) {
        // ----- LayerNorm row -----
        int row = blk;
        const float* xr = x + (size_t)row * DIM;
        float vals[3];
        float s = 0.f, s2 = 0.f;
#pragma unroll
        for (int i = 0; i < 3; i++) {
            float v = xr[threadIdx.x + i * 256];
            vals[i] = v; s += v; s2 += v * v;
        }
        __shared__ float sh1[32], sh2[32];
#pragma unroll
        for (int o = 16; o > 0; o >>= 1) {
            s  += __shfl_down_sync(0xffffffffu, s,  o);
            s2 += __shfl_down_sync(0xffffffffu, s2, o);
        }
        int lane = threadIdx.x & 31, wid = threadIdx.x >> 5;
        if (lane == 0) { sh1[wid] = s; sh2[wid] = s2; }
        __syncthreads();
        if (wid == 0) {
            s  = (lane < 8) ? sh1[lane] : 0.f;
            s2 = (lane < 8) ? sh2[lane] : 0.f;
#pragma unroll
            for (int o = 4; o > 0; o >>= 1) {
                s  += __shfl_down_sync(0xffffffffu, s,  o);
                s2 += __shfl_down_sync(0xffffffffu, s2, o);
            }
            if (lane == 0) { sh1[0] = s; sh2[0] = s2; }
        }
        __syncthreads();
        float mean = sh1[0] * (1.f / DIM);
        float var  = sh2[0] * (1.f / DIM) - mean * mean;
        float rstd = rsqrtf(var + LN_EPS);
#pragma unroll
        for (int i = 0; i < 3; i++) {
            int c = threadIdx.x + i * 256;
            g_xn[(size_t)row * DIM + c] = to_tf32((vals[i] - mean) * rstd * gam[c] + bet[c]);
        }
    } else if (blk < ROWS + RW_BLOCKS) {
        // ----- weight tf32 pre-round -----
        int i = (blk - ROWS) * 256 + threadIdx.x;
        const float4* src;
        float4* dst;
        int j;
        if (i < WQ4) { src = (const float4*)wq; j = i; dst = (float4*)g_wq; }
        else if (i < WQ4 + WO4) { src = (const float4*)wo; j = i - WQ4; dst = (float4*)g_wo; }
        else return;
        float4 v = src[j];
        v.x = to_tf32(v.x); v.y = to_tf32(v.y); v.z = to_tf32(v.z); v.w = to_tf32(v.w);
        dst[j] = v;
    } else {
        // ----- M = (-0.5*theta) @ gnn_w -----
        int t = threadIdx.x;
        if (t < HEADS * HEADS) {
            int i = t / HEADS, m = t % HEADS;
            float s = 0.f;
#pragma unroll
            for (int j = 0; j < HEADS; j++)
                s += (-0.5f * theta[i * HEADS + j]) * w[j * HEADS + m];
            g_M[t] = s;
        }
    }
}

// ---------------- QKV: BN=128, 2-stage (best-known), scatter to heads ------
__global__ __launch_bounds__(256, 2) void qkv_tc() {
    extern __shared__ float dynsm[];
    float* As = dynsm;
    float* Bs = dynsm + 2 * 128 * PADC;
    int nb = blockIdx.x, mb = blockIdx.y;
    float Cacc[64] = {};
    gemm_pipe<128, 2, false>(Cacc, g_xn + (size_t)mb * 128 * DIM, DIM,
                             g_wq + (size_t)nb * 128 * DIM, DIM, DIM, As, Bs);

    const int lane = threadIdx.x & 31, wid = threadIdx.x >> 5;
    const int g = lane >> 2, t = lane & 3;
    const int wr = wid >> 2, wc = wid & 3;
#pragma unroll
    for (int mi = 0; mi < 4; mi++) {
        int gi0 = mb * 128 + wr * 64 + mi * 16 + g;
#pragma unroll
        for (int ni = 0; ni < 4; ni++) {
            int j = nb * 128 + wc * 32 + ni * 8 + 2 * t;
            int which = j / INNER;
            int rc = j - which * INNER;
            int h = rc >> 6, d = rc & 63;
            const float* cp = &Cacc[(mi * 4 + ni) * 4];
#pragma unroll
            for (int half = 0; half < 2; half++) {
                int gi = gi0 + half * 8;
                int b = gi >> 10, n = gi & 1023;
                float c0 = to_tf32(cp[half * 2]), c1 = to_tf32(cp[half * 2 + 1]);
                if (which < 2) {
                    float* dst = (which == 0) ? g_q : g_k;
                    *(float2*)(dst + ((size_t)(b * HEADS + h) * SEQ + n) * DH + d)
                        = make_float2(c0, c1);
                } else {
                    float* p = g_vt + (size_t)(b * HEADS + h) * DH * SEQ + n;
                    p[(size_t)d * SEQ] = c0;
                    p[(size_t)(d + 1) * SEQ] = c1;
                }
            }
        }
    }
}

// ---------------- dots strip: q resident, 3-deep k ring --------------------
__global__ __launch_bounds__(256, 2) void dots_tc() {
    extern __shared__ float dynsm[];
    float* As = dynsm;                     // [2 chunks][128][PADC]  (q, resident)
    float* Bs = dynsm + 2 * 128 * PADC;    // [3 bufs][128][PADC]    (k ring)
    __shared__ float sred[128][4];
    const int split = blockIdx.x, mb = blockIdx.y, bz = blockIdx.z;
    const float* Aq = g_q + (size_t)bz * SEQ * DH + (size_t)mb * 128 * DH;
    const float* Bk = g_k + (size_t)bz * SEQ * DH;

    const int tid = threadIdx.x, wid = tid >> 5, lane = tid & 31;
    const int g = lane >> 2, t = lane & 3;
    const int wr = wid >> 2, wc = wid & 3;
    const int arow = tid >> 1, ac0 = (tid & 1) * 16;
    const int lq = lane & 7, lt = lane >> 3;
    const uint32_t sa = smem_u32(As);
    const uint32_t sb = smem_u32(Bs);
    const uint32_t a0 = sa + (uint32_t)((wr * 64 + (lt & 1) * 8 + lq) * PADC + (lt >> 1) * 4) * 4u;
    const uint32_t b0 = sb + (uint32_t)((wc * 32 + (lt >> 1) * 8 + lq) * PADC + (lt & 1) * 4) * 4u;

    // load q (both chunks) once — one group
#pragma unroll
    for (int ch = 0; ch < 2; ch++) {
        const float* ap = Aq + (size_t)arow * DH + ch * 32 + ac0;
        uint32_t da = sa + (uint32_t)(ch * 128 * PADC + arow * PADC + ac0) * 4u;
#pragma unroll
        for (int i = 0; i < 4; i++) CP_ASYNC16(da + i * 16, ap + i * 4);
    }
    CP_COMMIT();

    auto prefetch_k = [&](int gc) {
        int nb = split * NB_PER + (gc >> 1);
        int ch = gc & 1;
        const float* bp = Bk + ((size_t)nb * 128 + arow) * DH + ch * 32 + ac0;
        uint32_t db = sb + (uint32_t)((gc % 3) * 128 * PADC + arow * PADC + ac0) * 4u;
#pragma unroll
        for (int i = 0; i < 4; i++) CP_ASYNC16(db + i * 16, bp + i * 4);
        CP_COMMIT();
    };

    const int NCH = NB_PER * 2;
    prefetch_k(0);
    if (NCH > 1) prefetch_k(1);
    float rs0[4] = {}, rs1[4] = {};
    float Cacc[64];
    for (int gc = 0; gc < NCH; gc++) {
        if (gc < NCH - 1) CP_WAIT1(); else CP_WAIT0();
        __syncthreads();
        if (gc + 2 < NCH) prefetch_k(gc + 2);
        if ((gc & 1) == 0) {
#pragma unroll
            for (int i = 0; i < 64; i++) Cacc[i] = 0.f;
        }
        const uint32_t ab = a0 + (uint32_t)(gc & 1) * (128 * PADC * 4);
        const uint32_t bb = b0 + (uint32_t)(gc % 3) * (128 * PADC * 4);
#pragma unroll
        for (int ks = 0; ks < 4; ks++) {
            uint32_t af[4][4], bf[2][4];
#pragma unroll
            for (int mi = 0; mi < 4; mi++)
                LDSM_X4(af[mi][0], af[mi][1], af[mi][2], af[mi][3],
                        ab + mi * (16 * PADC * 4) + ks * 32);
#pragma unroll
            for (int p = 0; p < 2; p++)
                LDSM_X4(bf[p][0], bf[p][1], bf[p][2], bf[p][3],
                        bb + p * (16 * PADC * 4) + ks * 32);
#pragma unroll
            for (int mi = 0; mi < 4; mi++)
#pragma unroll
                for (int ni = 0; ni < 4; ni++)
                    mma_tf32(&Cacc[(mi * 4 + ni) * 4], af[mi], &bf[ni >> 1][(ni & 1) * 2]);
        }
        if ((gc & 1) == 1) {
            int nb = split * NB_PER + (gc >> 1);
#pragma unroll
            for (int mi = 0; mi < 4; mi++) {
                int row0 = mb * 128 + wr * 64 + mi * 16 + g;
#pragma unroll
                for (int ni = 0; ni < 4; ni++) {
                    int col = nb * 128 + wc * 32 + ni * 8 + 2 * t;
                    float* cp = &Cacc[(mi * 4 + ni) * 4];
                    float e0 = __expf(cp[0] * SCALE), e1 = __expf(cp[1] * SCALE);
                    float e2 = __expf(cp[2] * SCALE), e3 = __expf(cp[3] * SCALE);
                    rs0[mi] += e0 + e1; rs1[mi] += e2 + e3;
                    *(float2*)(g_attn + (size_t)bz * NN + (size_t)row0 * SEQ + col)
                        = make_float2(e0, e1);
                    *(float2*)(g_attn + (size_t)bz * NN + (size_t)(row0 + 8) * SEQ + col)
                        = make_float2(e2, e3);
                }
            }
        }
    }
#pragma unroll
    for (int mi = 0; mi < 4; mi++) {
#pragma unroll
        for (int o = 1; o < 4; o <<= 1) {
            rs0[mi] += __shfl_xor_sync(0xffffffffu, rs0[mi], o);
            rs1[mi] += __shfl_xor_sync(0xffffffffu, rs1[mi], o);
        }
        if (t == 0) {
            int rl = wr * 64 + mi * 16 + g;
            sred[rl][wc] = rs0[mi];
            sred[rl + 8][wc] = rs1[mi];
        }
    }
    __syncthreads();
    if (tid < 128) {
        float s = sred[tid][0] + sred[tid][1] + sred[tid][2] + sred[tid][3];
        g_psum[((size_t)bz * SEQ + mb * 128 + tid) * NSPLIT + split] = s;
    }
}

// ---------------- head-mix (float4) + g_O zeroing --------------------------
__global__ __launch_bounds__(256) void mix_kernel() {
    __shared__ float Ms[HEADS * HEADS];
    __shared__ float ri[HEADS];
    const int blk = blockIdx.x;           // 0..ROWS-1
    const int b = blk >> 10;
    const int row = blk & 1023;
    const int tid = threadIdx.x;
    // zero g_O for av's red.global accumulation (av runs strictly later)
    {
        size_t zi = (size_t)blk * 256 + tid;
        if (zi < (size_t)ROWS * INNER / 4)
            ((float4*)g_O)[zi] = make_float4(0.f, 0.f, 0.f, 0.f);
    }
    if (tid < HEADS * HEADS) Ms[tid] = g_M[tid];
    if (tid < HEADS) {
        const float* ps = g_psum + ((size_t)(b * HEADS + tid) * SEQ + row) * NSPLIT;
        float s = 0.f;
#pragma unroll
        for (int i = 0; i < NSPLIT; i++) s += ps[i];
        ri[tid] = 1.f / s;
    }
    __syncthreads();
    const size_t base = (size_t)b * HEADS * NN + (size_t)row * SEQ + tid * 4;
    float4 a[HEADS];
#pragma unroll
    for (int j = 0; j < HEADS; j++) {
        float4 v = *(const float4*)(g_attn + base + (size_t)j * NN);
        float r = ri[j];
        a[j] = make_float4(v.x * r, v.y * r, v.z * r, v.w * r);
    }
#pragma unroll
    for (int h = 0; h < HEADS; h++) {
        float4 s = make_float4(0.f, 0.f, 0.f, 0.f);
#pragma unroll
        for (int j = 0; j < HEADS; j++) {
            float m = Ms[h * HEADS + j];
            s.x += m * a[j].x; s.y += m * a[j].y;
            s.z += m * a[j].z; s.w += m * a[j].w;
        }
        float4 o = make_float4(to_tf32(a[h].x + fmaxf(s.x, 0.f)),
                               to_tf32(a[h].y + fmaxf(s.y, 0.f)),
                               to_tf32(a[h].z + fmaxf(s.z, 0.f)),
                               to_tf32(a[h].w + fmaxf(s.w, 0.f)));
        *(float4*)(g_P + base + (size_t)h * NN) = o;
    }
}

// ---------------- AV split-K: red.global.add into zeroed g_O ---------------
__global__ __launch_bounds__(256, 3) void av_tc() {
    extern __shared__ float dynsm[];
    float* As = dynsm;
    float* Bs = dynsm + 2 * 128 * PADC;
    int mb = blockIdx.x, bz = blockIdx.y, sp = blockIdx.z;
    const int koff = sp * (SEQ / KSPLIT_AV);
    float Cacc[32] = {};
    gemm_pipe<64, 2, false>(Cacc,
                            g_P + (size_t)bz * NN + (size_t)mb * 128 * SEQ + koff, SEQ,
                            g_vt + (size_t)bz * DH * SEQ + koff, SEQ,
                            SEQ / KSPLIT_AV, As, Bs);

    const int lane = threadIdx.x & 31, wid = threadIdx.x >> 5;
    const int g = lane >> 2, t = lane & 3;
    const int wr = wid >> 1, wc = wid & 1;
    int b = bz / HEADS, h = bz % HEADS;
#pragma unroll
    for (int mi = 0; mi < 2; mi++) {
        int n0 = mb * 128 + wr * 32 + mi * 16 + g;
#pragma unroll
        for (int ni = 0; ni < 4; ni++) {
            int d = wc * 32 + ni * 8 + 2 * t;
            float* cp = &Cacc[(mi * 4 + ni) * 4];
            float* p0 = g_O + (size_t)(b * SEQ + n0) * INNER + h * DH + d;
            float* p1 = g_O + (size_t)(b * SEQ + n0 + 8) * INNER + h * DH + d;
            REDADD(p0, cp[0]); REDADD(p0 + 1, cp[1]);
            REDADD(p1, cp[2]); REDADD(p1 + 1, cp[3]);
        }
    }
}

// ---------------- out projection (raw-fp32 A, cvt in frags) ----------------
__global__ __launch_bounds__(256, 3) void proj_tc(const float* __restrict__ bias,
                                                  float* __restrict__ out) {
    extern __shared__ float dynsm[];
    float* As = dynsm;
    float* Bs = dynsm + 2 * 128 * PADC;
    int nb = blockIdx.x, mb = blockIdx.y;
    float Cacc[32] = {};
    gemm_pipe<64, 2, true>(Cacc, g_O + (size_t)mb * 128 * INNER, INNER,
                           g_wo + (size_t)nb * 64 * INNER, INNER, INNER, As, Bs);

    const int lane = threadIdx.x & 31, wid = threadIdx.x >> 5;
    const int g = lane >> 2, t = lane & 3;
    const int wr = wid >> 1, wc = wid & 1;
#pragma unroll
    for (int mi = 0; mi < 2; mi++) {
        int gi = mb * 128 + wr * 32 + mi * 16 + g;
#pragma unroll
        for (int ni = 0; ni < 4; ni++) {
            int j = nb * 64 + wc * 32 + ni * 8 + 2 * t;
            float b0 = bias[j], b1 = bias[j + 1];
            float* cp = &Cacc[(mi * 4 + ni) * 4];
            *(float2*)(out + (size_t)gi * DIM + j) = make_float2(cp[0] + b0, cp[1] + b1);
            *(float2*)(out + (size_t)(gi + 8) * DIM + j) = make_float2(cp[2] + b0, cp[3] + b1);
        }
    }
}

// ---------------- launcher -------------------------------------------------
extern "C" void kernel_launch(void* const* d_in, const int* in_sizes, int n_in,
                              void* d_out, int out_size) {
    const float* x     = (const float*)d_in[0];
    const float* ln_g  = (const float*)d_in[1];
    const float* ln_b  = (const float*)d_in[2];
    const float* w_qkv = (const float*)d_in[3];
    const float* w_out = (const float*)d_in[4];
    const float* b_out = (const float*)d_in[5];
    const float* theta = (const float*)d_in[6];
    const float* gnn_w = (const float*)d_in[7];
    float* out = (float*)d_out;

    cudaFuncSetAttribute(qkv_tc,  cudaFuncAttributeMaxDynamicSharedMemorySize, SMEM128);
    cudaFuncSetAttribute(dots_tc, cudaFuncAttributeMaxDynamicSharedMemorySize, SMEM_DOTS);
    cudaFuncSetAttribute(av_tc,   cudaFuncAttributeMaxDynamicSharedMemorySize, SMEM64);
    cudaFuncSetAttribute(proj_tc, cudaFuncAttributeMaxDynamicSharedMemorySize, SMEM64);

    prep_kernel<<<ROWS + RW_BLOCKS + 1, 256>>>(x, ln_g, ln_b, w_qkv, w_out,
                                               theta, gnn_w);
    qkv_tc<<<dim3(18, 16), 256, SMEM128>>>();
    dots_tc<<<dim3(NSPLIT, 8, BH), 256, SMEM_DOTS>>>();
    mix_kernel<<<BATCH * SEQ, 256>>>();
    av_tc<<<dim3(8, BH, KSPLIT_AV), 256, SMEM64>>>();
    proj_tc<<<dim3(12, 16), 256, SMEM64>>>(b_out, out);
}

// round 17
// speedup vs baseline: 1.2295x; 1.1406x over previous
#include <cuda_runtime.h>
#include <cuda_fp16.h>
#include <cstdint>

#define DIM 768
#define HEADS 12
#define DH 64
#define INNER 768
#define BATCH 2
#define SEQ 1024
#define ROWS (BATCH*SEQ)      // 2048
#define NN (SEQ*SEQ)          // 1048576
#define BH (BATCH*HEADS)      // 24
#define SCALE 0.125f
#define LN_EPS 1e-5f
#define PADC 36               // fp32 chunk row stride (floats)
#define PADH 40               // fp16 chunk row stride (halves; 80B, 16B mult)
#define NSPLIT 4
#define NB_PER (8/NSPLIT)
#define KSPLIT_AV 2

// ---------------- scratch (device globals; no allocation allowed) ----------
__device__ float g_xn[ROWS*DIM];               // tf32-rounded
__device__ float g_wq[3*INNER*DIM];            // tf32-rounded w_qkv
__device__ float g_wo[DIM*INNER];              // tf32-rounded w_out
__device__ float g_q[BH*SEQ*DH];               // tf32-rounded
__device__ float g_k[BH*SEQ*DH];               // tf32-rounded
__device__ __half g_vth[BH*DH*SEQ];            // fp16, [bh][d][n]
__device__ __half g_attnh[(size_t)BH*NN];      // fp16 exp(logits)
__device__ __half g_Ph[(size_t)BH*NN];         // fp16 mixed weights
__device__ float g_psum[BH*SEQ*NSPLIT];
__device__ float g_O[ROWS*INNER];              // red.global accumulated
__device__ float g_M[HEADS*HEADS];

// ---------------- helpers --------------------------------------------------
__device__ __forceinline__ uint32_t smem_u32(const void* p) {
    uint32_t a;
    asm("{ .reg .u64 t; cvta.to.shared.u64 t, %1; cvt.u32.u64 %0, t; }"
        : "=r"(a) : "l"(p));
    return a;
}
__device__ __forceinline__ float to_tf32(float x) {
    float y;
    asm("cvt.rna.tf32.f32 %0, %1;" : "=f"(y) : "f"(x));
    return y;
}
__device__ __forceinline__ void mma_tf32(float* c, const uint32_t* a, const uint32_t* b) {
    asm volatile(
        "mma.sync.aligned.m16n8k8.row.col.f32.tf32.tf32.f32 "
        "{%0,%1,%2,%3}, {%4,%5,%6,%7}, {%8,%9}, {%0,%1,%2,%3};"
        : "+f"(c[0]), "+f"(c[1]), "+f"(c[2]), "+f"(c[3])
        : "r"(a[0]), "r"(a[1]), "r"(a[2]), "r"(a[3]), "r"(b[0]), "r"(b[1]));
}
__device__ __forceinline__ void mma_f16(float* c, const uint32_t* a,
                                        uint32_t b0, uint32_t b1) {
    asm volatile(
        "mma.sync.aligned.m16n8k16.row.col.f32.f16.f16.f32 "
        "{%0,%1,%2,%3}, {%4,%5,%6,%7}, {%8,%9}, {%0,%1,%2,%3};"
        : "+f"(c[0]), "+f"(c[1]), "+f"(c[2]), "+f"(c[3])
        : "r"(a[0]), "r"(a[1]), "r"(a[2]), "r"(a[3]), "r"(b0), "r"(b1));
}
#define LDSM_X4(r0, r1, r2, r3, addr) \
    asm volatile("ldmatrix.sync.aligned.m8n8.x4.shared.b16 {%0,%1,%2,%3}, [%4];" \
        : "=r"(r0), "=r"(r1), "=r"(r2), "=r"(r3) : "r"(addr))
#define CP_ASYNC16(dst, src) \
    asm volatile("cp.async.cg.shared.global [%0], [%1], 16;" \
        :: "r"(dst), "l"(src) : "memory")
#define CP_COMMIT()  asm volatile("cp.async.commit_group;" ::: "memory")
#define CP_WAIT1()   asm volatile("cp.async.wait_group 1;" ::: "memory")
#define CP_WAIT0()   asm volatile("cp.async.wait_group 0;" ::: "memory")
#define REDADD(addr, v) \
    asm volatile("red.global.add.f32 [%0], %1;" :: "l"(addr), "f"(v) : "memory")

// ---- pipelined tf32 mma core: D[128,BN]=A[128,K]@B[BN,K]^T (fp32 ops) -----
template<int BN, int STAGES, bool CVTA>
__device__ __forceinline__ void gemm_pipe(float* Cacc,
                                          const float* __restrict__ A, int lda,
                                          const float* __restrict__ B, int ldb,
                                          int K, float* As, float* Bs) {
    constexpr int WC = BN / 32;
    constexpr int WR = 8 / WC;
    constexpr int WM = 128 / WR;
    constexpr int MT = WM / 16;
    constexpr int BTPR = 256 / BN;
    constexpr int BSEG = 32 / BTPR;
    constexpr int PF = STAGES - 1;

    const int tid = threadIdx.x, wid = tid >> 5, lane = tid & 31;
    const int wr = wid / WC, wc = wid % WC;
    const int wm0 = wr * WM, wn0 = wc * 32;
    const int arow = tid >> 1, ac0 = (tid & 1) * 16;
    const int brow = tid / BTPR, bc0 = (tid % BTPR) * BSEG;
    const int lq = lane & 7, lt = lane >> 3;

    const uint32_t sa = smem_u32(As);
    const uint32_t sb = smem_u32(Bs);
    const uint32_t a0 = sa + (uint32_t)((wm0 + (lt & 1) * 8 + lq) * PADC + (lt >> 1) * 4) * 4u;
    const uint32_t b0 = sb + (uint32_t)((wn0 + (lt >> 1) * 8 + lq) * PADC + (lt & 1) * 4) * 4u;
    const int nch = K >> 5;

    auto prefetch = [&](int c, int buf) {
        const float* ap = A + (size_t)arow * lda + c * 32 + ac0;
        uint32_t da = sa + (uint32_t)(buf * 128 * PADC + arow * PADC + ac0) * 4u;
#pragma unroll
        for (int i = 0; i < 4; i++) CP_ASYNC16(da + i * 16, ap + i * 4);
        const float* bp = B + (size_t)brow * ldb + c * 32 + bc0;
        uint32_t db = sb + (uint32_t)(buf * BN * PADC + brow * PADC + bc0) * 4u;
#pragma unroll
        for (int i = 0; i < BSEG / 4; i++) CP_ASYNC16(db + i * 16, bp + i * 4);
        CP_COMMIT();
    };

    prefetch(0, 0);
    if (STAGES >= 3 && nch > 1) prefetch(1, 1);
    for (int c = 0; c < nch; c++) {
        if (STAGES >= 3 && c < nch - 1) CP_WAIT1(); else CP_WAIT0();
        __syncthreads();
        if (c + PF < nch) prefetch(c + PF, (c + PF) % STAGES);
        const uint32_t ab = a0 + (uint32_t)(c % STAGES) * (128 * PADC * 4);
        const uint32_t bb = b0 + (uint32_t)(c % STAGES) * (BN * PADC * 4);
#pragma unroll
        for (int ks = 0; ks < 4; ks++) {
            uint32_t af[MT][4], bf[2][4];
#pragma unroll
            for (int mi = 0; mi < MT; mi++) {
                LDSM_X4(af[mi][0], af[mi][1], af[mi][2], af[mi][3],
                        ab + mi * (16 * PADC * 4) + ks * 32);
                if (CVTA) {
#pragma unroll
                    for (int r = 0; r < 4; r++)
                        af[mi][r] = __float_as_uint(to_tf32(__uint_as_float(af[mi][r])));
                }
            }
#pragma unroll
            for (int p = 0; p < 2; p++)
                LDSM_X4(bf[p][0], bf[p][1], bf[p][2], bf[p][3],
                        bb + p * (16 * PADC * 4) + ks * 32);
#pragma unroll
            for (int mi = 0; mi < MT; mi++)
#pragma unroll
                for (int ni = 0; ni < 4; ni++)
                    mma_tf32(&Cacc[(mi * 4 + ni) * 4], af[mi], &bf[ni >> 1][(ni & 1) * 2]);
        }
    }
    __syncthreads();
}

#define SMEM128 ((2*128 + 2*128) * PADC * 4)    // 73728 B
#define SMEM_DOTS ((2*128 + 3*128) * PADC * 4)  // 92160 B
#define SMEM64  ((2*128 + 2*64)  * PADC * 4)    // 55296 B
#define SMEM_AV ((2*128 + 2*64) * PADH * 2)     // 30720 B (fp16)

// ---------------- prep: ln + weight rounding + M ---------------------------
#define WQ4 ((3*INNER*DIM)/4)
#define WO4 ((DIM*INNER)/4)
#define RW_BLOCKS ((WQ4 + WO4 + 255) / 256)
__global__ __launch_bounds__(256) void prep_kernel(
        const float* __restrict__ x, const float* __restrict__ gam,
        const float* __restrict__ bet, const float* __restrict__ wq,
        const float* __restrict__ wo, const float* __restrict__ theta,
        const float* __restrict__ w) {
    int blk = blockIdx.x;
    if (blk < ROWS) {
        int row = blk;
        const float* xr = x + (size_t)row * DIM;
        float vals[3];
        float s = 0.f, s2 = 0.f;
#pragma unroll
        for (int i = 0; i < 3; i++) {
            float v = xr[threadIdx.x + i * 256];
            vals[i] = v; s += v; s2 += v * v;
        }
        __shared__ float sh1[32], sh2[32];
#pragma unroll
        for (int o = 16; o > 0; o >>= 1) {
            s  += __shfl_down_sync(0xffffffffu, s,  o);
            s2 += __shfl_down_sync(0xffffffffu, s2, o);
        }
        int lane = threadIdx.x & 31, wid = threadIdx.x >> 5;
        if (lane == 0) { sh1[wid] = s; sh2[wid] = s2; }
        __syncthreads();
        if (wid == 0) {
            s  = (lane < 8) ? sh1[lane] : 0.f;
            s2 = (lane < 8) ? sh2[lane] : 0.f;
#pragma unroll
            for (int o = 4; o > 0; o >>= 1) {
                s  += __shfl_down_sync(0xffffffffu, s,  o);
                s2 += __shfl_down_sync(0xffffffffu, s2, o);
            }
            if (lane == 0) { sh1[0] = s; sh2[0] = s2; }
        }
        __syncthreads();
        float mean = sh1[0] * (1.f / DIM);
        float var  = sh2[0] * (1.f / DIM) - mean * mean;
        float rstd = rsqrtf(var + LN_EPS);
#pragma unroll
        for (int i = 0; i < 3; i++) {
            int c = threadIdx.x + i * 256;
            g_xn[(size_t)row * DIM + c] = to_tf32((vals[i] - mean) * rstd * gam[c] + bet[c]);
        }
    } else if (blk < ROWS + RW_BLOCKS) {
        int i = (blk - ROWS) * 256 + threadIdx.x;
        const float4* src;
        float4* dst;
        int j;
        if (i < WQ4) { src = (const float4*)wq; j = i; dst = (float4*)g_wq; }
        else if (i < WQ4 + WO4) { src = (const float4*)wo; j = i - WQ4; dst = (float4*)g_wo; }
        else return;
        float4 v = src[j];
        v.x = to_tf32(v.x); v.y = to_tf32(v.y); v.z = to_tf32(v.z); v.w = to_tf32(v.w);
        dst[j] = v;
    } else {
        int t = threadIdx.x;
        if (t < HEADS * HEADS) {
            int i = t / HEADS, m = t % HEADS;
            float s = 0.f;
#pragma unroll
            for (int j = 0; j < HEADS; j++)
                s += (-0.5f * theta[i * HEADS + j]) * w[j * HEADS + m];
            g_M[t] = s;
        }
    }
}

// ---------------- QKV: BN=128, 2-stage, scatter (v -> fp16 transposed) -----
__global__ __launch_bounds__(256, 2) void qkv_tc() {
    extern __shared__ float dynsm[];
    float* As = dynsm;
    float* Bs = dynsm + 2 * 128 * PADC;
    int nb = blockIdx.x, mb = blockIdx.y;
    float Cacc[64] = {};
    gemm_pipe<128, 2, false>(Cacc, g_xn + (size_t)mb * 128 * DIM, DIM,
                             g_wq + (size_t)nb * 128 * DIM, DIM, DIM, As, Bs);

    const int lane = threadIdx.x & 31, wid = threadIdx.x >> 5;
    const int g = lane >> 2, t = lane & 3;
    const int wr = wid >> 2, wc = wid & 3;
#pragma unroll
    for (int mi = 0; mi < 4; mi++) {
        int gi0 = mb * 128 + wr * 64 + mi * 16 + g;
#pragma unroll
        for (int ni = 0; ni < 4; ni++) {
            int j = nb * 128 + wc * 32 + ni * 8 + 2 * t;
            int which = j / INNER;
            int rc = j - which * INNER;
            int h = rc >> 6, d = rc & 63;
            const float* cp = &Cacc[(mi * 4 + ni) * 4];
#pragma unroll
            for (int half = 0; half < 2; half++) {
                int gi = gi0 + half * 8;
                int b = gi >> 10, n = gi & 1023;
                if (which < 2) {
                    float* dst = (which == 0) ? g_q : g_k;
                    *(float2*)(dst + ((size_t)(b * HEADS + h) * SEQ + n) * DH + d)
                        = make_float2(to_tf32(cp[half * 2]), to_tf32(cp[half * 2 + 1]));
                } else {
                    __half* p = g_vth + (size_t)(b * HEADS + h) * DH * SEQ + n;
                    p[(size_t)d * SEQ] = __float2half_rn(cp[half * 2]);
                    p[(size_t)(d + 1) * SEQ] = __float2half_rn(cp[half * 2 + 1]);
                }
            }
        }
    }
}

// ---------------- dots strip: q resident, 3-deep k ring, fp16 attn out -----
__global__ __launch_bounds__(256, 2) void dots_tc() {
    extern __shared__ float dynsm[];
    float* As = dynsm;
    float* Bs = dynsm + 2 * 128 * PADC;
    __shared__ float sred[128][4];
    const int split = blockIdx.x, mb = blockIdx.y, bz = blockIdx.z;
    const float* Aq = g_q + (size_t)bz * SEQ * DH + (size_t)mb * 128 * DH;
    const float* Bk = g_k + (size_t)bz * SEQ * DH;

    const int tid = threadIdx.x, wid = tid >> 5, lane = tid & 31;
    const int g = lane >> 2, t = lane & 3;
    const int wr = wid >> 2, wc = wid & 3;
    const int arow = tid >> 1, ac0 = (tid & 1) * 16;
    const int lq = lane & 7, lt = lane >> 3;
    const uint32_t sa = smem_u32(As);
    const uint32_t sb = smem_u32(Bs);
    const uint32_t a0 = sa + (uint32_t)((wr * 64 + (lt & 1) * 8 + lq) * PADC + (lt >> 1) * 4) * 4u;
    const uint32_t b0 = sb + (uint32_t)((wc * 32 + (lt >> 1) * 8 + lq) * PADC + (lt & 1) * 4) * 4u;

#pragma unroll
    for (int ch = 0; ch < 2; ch++) {
        const float* ap = Aq + (size_t)arow * DH + ch * 32 + ac0;
        uint32_t da = sa + (uint32_t)(ch * 128 * PADC + arow * PADC + ac0) * 4u;
#pragma unroll
        for (int i = 0; i < 4; i++) CP_ASYNC16(da + i * 16, ap + i * 4);
    }
    CP_COMMIT();

    auto prefetch_k = [&](int gc) {
        int nb = split * NB_PER + (gc >> 1);
        int ch = gc & 1;
        const float* bp = Bk + ((size_t)nb * 128 + arow) * DH + ch * 32 + ac0;
        uint32_t db = sb + (uint32_t)((gc % 3) * 128 * PADC + arow * PADC + ac0) * 4u;
#pragma unroll
        for (int i = 0; i < 4; i++) CP_ASYNC16(db + i * 16, bp + i * 4);
        CP_COMMIT();
    };

    const int NCH = NB_PER * 2;
    prefetch_k(0);
    if (NCH > 1) prefetch_k(1);
    float rs0[4] = {}, rs1[4] = {};
    float Cacc[64];
    for (int gc = 0; gc < NCH; gc++) {
        if (gc < NCH - 1) CP_WAIT1(); else CP_WAIT0();
        __syncthreads();
        if (gc + 2 < NCH) prefetch_k(gc + 2);
        if ((gc & 1) == 0) {
#pragma unroll
            for (int i = 0; i < 64; i++) Cacc[i] = 0.f;
        }
        const uint32_t ab = a0 + (uint32_t)(gc & 1) * (128 * PADC * 4);
        const uint32_t bb = b0 + (uint32_t)(gc % 3) * (128 * PADC * 4);
#pragma unroll
        for (int ks = 0; ks < 4; ks++) {
            uint32_t af[4][4], bf[2][4];
#pragma unroll
            for (int mi = 0; mi < 4; mi++)
                LDSM_X4(af[mi][0], af[mi][1], af[mi][2], af[mi][3],
                        ab + mi * (16 * PADC * 4) + ks * 32);
#pragma unroll
            for (int p = 0; p < 2; p++)
                LDSM_X4(bf[p][0], bf[p][1], bf[p][2], bf[p][3],
                        bb + p * (16 * PADC * 4) + ks * 32);
#pragma unroll
            for (int mi = 0; mi < 4; mi++)
#pragma unroll
                for (int ni = 0; ni < 4; ni++)
                    mma_tf32(&Cacc[(mi * 4 + ni) * 4], af[mi], &bf[ni >> 1][(ni & 1) * 2]);
        }
        if ((gc & 1) == 1) {
            int nb = split * NB_PER + (gc >> 1);
#pragma unroll
            for (int mi = 0; mi < 4; mi++) {
                int row0 = mb * 128 + wr * 64 + mi * 16 + g;
#pragma unroll
                for (int ni = 0; ni < 4; ni++) {
                    int col = nb * 128 + wc * 32 + ni * 8 + 2 * t;
                    float* cp = &Cacc[(mi * 4 + ni) * 4];
                    float e0 = __expf(cp[0] * SCALE), e1 = __expf(cp[1] * SCALE);
                    float e2 = __expf(cp[2] * SCALE), e3 = __expf(cp[3] * SCALE);
                    rs0[mi] += e0 + e1; rs1[mi] += e2 + e3;
                    *(__half2*)(g_attnh + (size_t)bz * NN + (size_t)row0 * SEQ + col)
                        = __floats2half2_rn(e0, e1);
                    *(__half2*)(g_attnh + (size_t)bz * NN + (size_t)(row0 + 8) * SEQ + col)
                        = __floats2half2_rn(e2, e3);
                }
            }
        }
    }
#pragma unroll
    for (int mi = 0; mi < 4; mi++) {
#pragma unroll
        for (int o = 1; o < 4; o <<= 1) {
            rs0[mi] += __shfl_xor_sync(0xffffffffu, rs0[mi], o);
            rs1[mi] += __shfl_xor_sync(0xffffffffu, rs1[mi], o);
        }
        if (t == 0) {
            int rl = wr * 64 + mi * 16 + g;
            sred[rl][wc] = rs0[mi];
            sred[rl + 8][wc] = rs1[mi];
        }
    }
    __syncthreads();
    if (tid < 128) {
        float s = sred[tid][0] + sred[tid][1] + sred[tid][2] + sred[tid][3];
        g_psum[((size_t)bz * SEQ + mb * 128 + tid) * NSPLIT + split] = s;
    }
}

// ---------------- head-mix (fp16 in/out) + g_O zeroing ---------------------
__global__ __launch_bounds__(256) void mix_kernel() {
    __shared__ float Ms[HEADS * HEADS];
    __shared__ float ri[HEADS];
    const int blk = blockIdx.x;
    const int b = blk >> 10;
    const int row = blk & 1023;
    const int tid = threadIdx.x;
    {
        size_t zi = (size_t)blk * 256 + tid;
        if (zi < (size_t)ROWS * INNER / 4)
            ((float4*)g_O)[zi] = make_float4(0.f, 0.f, 0.f, 0.f);
    }
    if (tid < HEADS * HEADS) Ms[tid] = g_M[tid];
    if (tid < HEADS) {
        const float* ps = g_psum + ((size_t)(b * HEADS + tid) * SEQ + row) * NSPLIT;
        float s = 0.f;
#pragma unroll
        for (int i = 0; i < NSPLIT; i++) s += ps[i];
        ri[tid] = 1.f / s;
    }
    __syncthreads();
    const size_t base = (size_t)b * HEADS * NN + (size_t)row * SEQ + tid * 4;
    float4 a[HEADS];
#pragma unroll
    for (int j = 0; j < HEADS; j++) {
        const __half2* pa = (const __half2*)(g_attnh + base + (size_t)j * NN);
        float2 lo = __half22float2(pa[0]);
        float2 hi = __half22float2(pa[1]);
        float r = ri[j];
        a[j] = make_float4(lo.x * r, lo.y * r, hi.x * r, hi.y * r);
    }
#pragma unroll
    for (int h = 0; h < HEADS; h++) {
        float4 s = make_float4(0.f, 0.f, 0.f, 0.f);
#pragma unroll
        for (int j = 0; j < HEADS; j++) {
            float m = Ms[h * HEADS + j];
            s.x += m * a[j].x; s.y += m * a[j].y;
            s.z += m * a[j].z; s.w += m * a[j].w;
        }
        __half2* pp = (__half2*)(g_Ph + base + (size_t)h * NN);
        pp[0] = __floats2half2_rn(a[h].x + fmaxf(s.x, 0.f), a[h].y + fmaxf(s.y, 0.f));
        pp[1] = __floats2half2_rn(a[h].z + fmaxf(s.z, 0.f), a[h].w + fmaxf(s.w, 0.f));
    }
}

// ---------------- AV split-K (fp16 HMMA): red.global into g_O --------------
__global__ __launch_bounds__(256, 3) void av_tc() {
    extern __shared__ __half dynsmh[];
    __half* Ah = dynsmh;                       // [2][128][PADH]
    __half* Bh = dynsmh + 2 * 128 * PADH;      // [2][64][PADH]
    int mb = blockIdx.x, bz = blockIdx.y, sp = blockIdx.z;
    const int koff = sp * (SEQ / KSPLIT_AV);
    const __half* A = g_Ph + (size_t)bz * NN + (size_t)mb * 128 * SEQ + koff;
    const __half* B = g_vth + (size_t)bz * DH * SEQ + koff;

    const int tid = threadIdx.x, wid = tid >> 5, lane = tid & 31;
    const int g = lane >> 2, t = lane & 3;
    const int wr = wid >> 1, wc = wid & 1;
    const int wm0 = wr * 32, wn0 = wc * 32;
    const int arow = tid >> 1, ac0 = (tid & 1) * 16;   // halves
    const int brow = tid >> 2, bc0 = (tid & 3) * 8;    // halves
    const int lq = lane & 7, lt = lane >> 3;

    const uint32_t sa = smem_u32(Ah);
    const uint32_t sb = smem_u32(Bh);
    // ldmatrix lane bases (halves *2 bytes): tile row lq, tile select lt
    const uint32_t a0 = sa + (uint32_t)((wm0 + (lt & 1) * 8 + lq) * PADH + (lt >> 1) * 8) * 2u;
    const uint32_t b00 = sb + (uint32_t)((wn0 + (lt & 1) * 8 + lq) * PADH + (lt >> 1) * 8) * 2u;
    const uint32_t b01 = sb + (uint32_t)((wn0 + 16 + (lt & 1) * 8 + lq) * PADH + (lt >> 1) * 8) * 2u;

    auto prefetch = [&](int c, int buf) {
        const __half* ap = A + (size_t)arow * SEQ + c * 32 + ac0;
        uint32_t da = sa + (uint32_t)(buf * 128 * PADH + arow * PADH + ac0) * 2u;
        CP_ASYNC16(da, ap);
        CP_ASYNC16(da + 16, ap + 8);
        const __half* bp = B + (size_t)brow * SEQ + c * 32 + bc0;
        uint32_t db = sb + (uint32_t)(buf * 64 * PADH + brow * PADH + bc0) * 2u;
        CP_ASYNC16(db, bp);
        CP_COMMIT();
    };

    const int nch = (SEQ / KSPLIT_AV) >> 5;   // 16 chunks of 32 halves
    float Cacc[32] = {};
    prefetch(0, 0);
    for (int c = 0; c < nch; c++) {
        CP_WAIT0();
        __syncthreads();
        if (c + 1 < nch) prefetch(c + 1, (c + 1) & 1);
        const uint32_t ab = a0 + (uint32_t)(c & 1) * (128 * PADH * 2);
        const uint32_t bb0 = b00 + (uint32_t)(c & 1) * (64 * PADH * 2);
        const uint32_t bb1 = b01 + (uint32_t)(c & 1) * (64 * PADH * 2);
#pragma unroll
        for (int ks = 0; ks < 2; ks++) {        // k16 steps
            uint32_t af[2][4], bf[2][4];
#pragma unroll
            for (int mi = 0; mi < 2; mi++)
                LDSM_X4(af[mi][0], af[mi][1], af[mi][2], af[mi][3],
                        ab + mi * (16 * PADH * 2) + ks * 32);
            LDSM_X4(bf[0][0], bf[0][1], bf[0][2], bf[0][3], bb0 + ks * 32);
            LDSM_X4(bf[1][0], bf[1][1], bf[1][2], bf[1][3], bb1 + ks * 32);
#pragma unroll
            for (int mi = 0; mi < 2; mi++)
#pragma unroll
                for (int ni = 0; ni < 4; ni++)
                    mma_f16(&Cacc[(mi * 4 + ni) * 4], af[mi],
                            bf[ni >> 1][ni & 1], bf[ni >> 1][(ni & 1) + 2]);
        }
    }
    __syncthreads();

    int b = bz / HEADS, h = bz % HEADS;
#pragma unroll
    for (int mi = 0; mi < 2; mi++) {
        int n0 = mb * 128 + wr * 32 + mi * 16 + g;
#pragma unroll
        for (int ni = 0; ni < 4; ni++) {
            int d = wc * 32 + ni * 8 + 2 * t;
            float* cp = &Cacc[(mi * 4 + ni) * 4];
            float* p0 = g_O + (size_t)(b * SEQ + n0) * INNER + h * DH + d;
            float* p1 = g_O + (size_t)(b * SEQ + n0 + 8) * INNER + h * DH + d;
            REDADD(p0, cp[0]); REDADD(p0 + 1, cp[1]);
            REDADD(p1, cp[2]); REDADD(p1 + 1, cp[3]);
        }
    }
}

// ---------------- out projection (raw-fp32 A, cvt in frags) ----------------
__global__ __launch_bounds__(256, 3) void proj_tc(const float* __restrict__ bias,
                                                  float* __restrict__ out) {
    extern __shared__ float dynsm[];
    float* As = dynsm;
    float* Bs = dynsm + 2 * 128 * PADC;
    int nb = blockIdx.x, mb = blockIdx.y;
    float Cacc[32] = {};
    gemm_pipe<64, 2, true>(Cacc, g_O + (size_t)mb * 128 * INNER, INNER,
                           g_wo + (size_t)nb * 64 * INNER, INNER, INNER, As, Bs);

    const int lane = threadIdx.x & 31, wid = threadIdx.x >> 5;
    const int g = lane >> 2, t = lane & 3;
    const int wr = wid >> 1, wc = wid & 1;
#pragma unroll
    for (int mi = 0; mi < 2; mi++) {
        int gi = mb * 128 + wr * 32 + mi * 16 + g;
#pragma unroll
        for (int ni = 0; ni < 4; ni++) {
            int j = nb * 64 + wc * 32 + ni * 8 + 2 * t;
            float b0 = bias[j], b1 = bias[j + 1];
            float* cp = &Cacc[(mi * 4 + ni) * 4];
            *(float2*)(out + (size_t)gi * DIM + j) = make_float2(cp[0] + b0, cp[1] + b1);
            *(float2*)(out + (size_t)(gi + 8) * DIM + j) = make_float2(cp[2] + b0, cp[3] + b1);
        }
    }
}

// ---------------- launcher -------------------------------------------------
extern "C" void kernel_launch(void* const* d_in, const int* in_sizes, int n_in,
                              void* d_out, int out_size) {
    const float* x     = (const float*)d_in[0];
    const float* ln_g  = (const float*)d_in[1];
    const float* ln_b  = (const float*)d_in[2];
    const float* w_qkv = (const float*)d_in[3];
    const float* w_out = (const float*)d_in[4];
    const float* b_out = (const float*)d_in[5];
    const float* theta = (const float*)d_in[6];
    const float* gnn_w = (const float*)d_in[7];
    float* out = (float*)d_out;

    cudaFuncSetAttribute(qkv_tc,  cudaFuncAttributeMaxDynamicSharedMemorySize, SMEM128);
    cudaFuncSetAttribute(dots_tc, cudaFuncAttributeMaxDynamicSharedMemorySize, SMEM_DOTS);
    cudaFuncSetAttribute(av_tc,   cudaFuncAttributeMaxDynamicSharedMemorySize, SMEM_AV);
    cudaFuncSetAttribute(proj_tc, cudaFuncAttributeMaxDynamicSharedMemorySize, SMEM64);

    prep_kernel<<<ROWS + RW_BLOCKS + 1, 256>>>(x, ln_g, ln_b, w_qkv, w_out,
                                               theta, gnn_w);
    qkv_tc<<<dim3(18, 16), 256, SMEM128>>>();
    dots_tc<<<dim3(NSPLIT, 8, BH), 256, SMEM_DOTS>>>();
    mix_kernel<<<BATCH * SEQ, 256>>>();
    av_tc<<<dim3(8, BH, KSPLIT_AV), 256, SMEM_AV>>>();
    proj_tc<<<dim3(12, 16), 256, SMEM64>>>(b_out, out);
}